// round 9
// baseline (speedup 1.0000x reference)
#include <cuda_runtime.h>
#include <cuda_fp16.h>
#include <cstdint>
#include <cstddef>

// ---------------- problem constants (fixed shapes) ----------------
#define NN    8000
#define EE    32000
#define ETOT  40000
#define GG    256
#define FF    680
#define HH    10
#define HFD   6800
#define HF2   13600

#define MP_G  8064
#define KP1   704
#define KP2   6848
#define KPM   13632
#define NPAD  6912

#define PCH   14

// ---------------- scratch ----------------
__device__ float g_xh [(size_t)NN * HFD];
__device__ float g_xw [(size_t)NN * HFD];
__device__ float g_h2 [(size_t)NN * HFD];
__device__ float g_als[NN * HH];
__device__ float g_ald[NN * HH];
__device__ float g_alpha[(size_t)ETOT * HH];
__device__ int   g_cnt[NN];
__device__ int   g_cur[NN];
__device__ int   g_start[NN + 1];
__device__ int   g_esrc[ETOT];
__device__ float g_dinv[NN];
__device__ int   g_pstart[GG];
__device__ int   g_pend[GG];
__device__ int   g_pcnt[GG];
__device__ float g_mlp1[GG * 512];
__device__ float g_mlp2[GG * 128];

// fp16 split panels: A=[hi|lo], Bt=[hi|lo] along K (each segment KP wide)
__device__ __half s_a2[(size_t)MP_G * (2 * KP2)];
__device__ __half s_b2[(size_t)NPAD * (2 * KP2)];

// ---------------- PTX helpers ----------------
__device__ __forceinline__ uint32_t smem_u32(const void* p) {
    uint32_t a;
    asm("{ .reg .u64 t; cvta.to.shared.u64 t, %1; cvt.u32.u64 %0, t; }" : "=r"(a) : "l"(p));
    return a;
}

__device__ __forceinline__ void cp16(uint32_t dst, const void* src) {
    asm volatile("cp.async.cg.shared.global [%0], [%1], 16;" :: "r"(dst), "l"(src));
}
#define CP_COMMIT() asm volatile("cp.async.commit_group;" ::: "memory")
__device__ __forceinline__ void cp_wait(int pend) {
    if (pend <= 0)      asm volatile("cp.async.wait_group 0;" ::: "memory");
    else                asm volatile("cp.async.wait_group 1;" ::: "memory");
}

__device__ __forceinline__ void ldsm4(uint32_t* r, uint32_t addr) {
    asm volatile("ldmatrix.sync.aligned.m8n8.x4.shared.b16 {%0,%1,%2,%3}, [%4];"
                 : "=r"(r[0]), "=r"(r[1]), "=r"(r[2]), "=r"(r[3]) : "r"(addr));
}

// fp16 x fp16 -> fp32 accumulators (main term)
__device__ __forceinline__ void mma_f32acc(float* d, const uint32_t* a, uint32_t b0, uint32_t b1) {
    asm volatile("mma.sync.aligned.m16n8k16.row.col.f32.f16.f16.f32 "
                 "{%0,%1,%2,%3}, {%4,%5,%6,%7}, {%8,%9}, {%0,%1,%2,%3};"
                 : "+f"(d[0]), "+f"(d[1]), "+f"(d[2]), "+f"(d[3])
                 : "r"(a[0]), "r"(a[1]), "r"(a[2]), "r"(a[3]), "r"(b0), "r"(b1));
}

// fp16 x fp16 -> fp16 accumulators (correction terms; 2 regs = packed half2 pairs)
__device__ __forceinline__ void mma_f16acc(uint32_t* d, const uint32_t* a, uint32_t b0, uint32_t b1) {
    asm volatile("mma.sync.aligned.m16n8k16.row.col.f16.f16.f16.f16 "
                 "{%0,%1}, {%2,%3,%4,%5}, {%6,%7}, {%0,%1};"
                 : "+r"(d[0]), "+r"(d[1])
                 : "r"(a[0]), "r"(a[1]), "r"(a[2]), "r"(a[3]), "r"(b0), "r"(b1));
}

__device__ __forceinline__ uint32_t sm_tile_off(int row, int chunk) {
    return (uint32_t)(row * 64 + ((chunk ^ ((row >> 1) & 3)) << 4));
}

// ---------------- fp16 3-term GEMM: hi*hi (f32acc) + lo*hi + hi*lo (f16acc) ----------------
#define BM 128
#define BN 128
#define BK 32
#define STG 3
#define SUB_BYTES   8192
#define STAGE_BYTES 32768
#define SMEM_MMA (STG * STAGE_BYTES)

__global__ __launch_bounds__(256, 1) void mma_gemm(
    const __half* __restrict__ A2, const __half* __restrict__ B2,
    const float* __restrict__ bias, float* __restrict__ C,
    int M, int N, int ldc, int KP, int tiles_m, int tiles_n, int flags)
{
    extern __shared__ char smem[];
    uint32_t sb = smem_u32(smem);
    const int tid = threadIdx.x;
    const int wid = tid >> 5;
    const int lane = tid & 31;
    const int warp_m = wid & 3;
    const int warp_n = wid >> 2;

    int gm, gn;
    {
        const int GM = 8;
        int bid = blockIdx.x;
        int per = GM * tiles_n;
        int grp = bid / per;
        int fm  = grp * GM;
        int gsz = tiles_m - fm; if (gsz > GM) gsz = GM;
        int r = bid - grp * per;
        gm = fm + r % gsz;
        gn = r / gsz;
    }

    const int CH = KP / BK;
    const int KA2 = 2 * KP;

    const int lrow = tid >> 1;
    const int lc0  = (tid & 1) * 2;
    const __half* pA = A2 + (size_t)(gm * BM + lrow) * KA2 + lc0 * 8;
    const __half* pB = B2 + (size_t)(gn * BN + lrow) * KA2 + lc0 * 8;
    const uint32_t so0 = sm_tile_off(lrow, lc0);
    const uint32_t so1 = so0 ^ 16;

    const uint32_t aoff00 = sm_tile_off(warp_m * 32 + (lane & 15), (lane >> 4));
    const uint32_t boff00 = 2 * SUB_BYTES + sm_tile_off(warp_n * 64 + (lane & 15), (lane >> 4));

    float acc[2][8][4];
    uint32_t hacc[2][8][2];
#pragma unroll
    for (int mi = 0; mi < 2; mi++)
#pragma unroll
        for (int ni = 0; ni < 8; ni++) {
#pragma unroll
            for (int j = 0; j < 4; j++) acc[mi][ni][j] = 0.f;
            hacc[mi][ni][0] = 0u; hacc[mi][ni][1] = 0u;
        }

    // preload chunks 0,1
#pragma unroll
    for (int c = 0; c < 2 && c < CH; c++) {
        uint32_t stb = sb + c * STAGE_BYTES;
        int ko = c * BK;
        cp16(stb + so0,                 pA + ko);
        cp16(stb + so1,                 pA + ko + 8);
        cp16(stb + SUB_BYTES + so0,     pA + KP + ko);
        cp16(stb + SUB_BYTES + so1,     pA + KP + ko + 8);
        cp16(stb + 2 * SUB_BYTES + so0, pB + ko);
        cp16(stb + 2 * SUB_BYTES + so1, pB + ko + 8);
        cp16(stb + 3 * SUB_BYTES + so0, pB + KP + ko);
        cp16(stb + 3 * SUB_BYTES + so1, pB + KP + ko + 8);
        CP_COMMIT();
    }

    int s = 0;
    int sload = 2;
    for (int c = 0; c < CH; c++) {
        cp_wait((CH - 1 - c) >= 1 ? 1 : 0);
        __syncthreads();

        if (c + 2 < CH) {
            uint32_t dtb = sb + sload * STAGE_BYTES;
            int ko = (c + 2) * BK;
            cp16(dtb + so0,                 pA + ko);
            cp16(dtb + so1,                 pA + ko + 8);
            cp16(dtb + SUB_BYTES + so0,     pA + KP + ko);
            cp16(dtb + SUB_BYTES + so1,     pA + KP + ko + 8);
            cp16(dtb + 2 * SUB_BYTES + so0, pB + ko);
            cp16(dtb + 2 * SUB_BYTES + so1, pB + ko + 8);
            cp16(dtb + 3 * SUB_BYTES + so0, pB + KP + ko);
            cp16(dtb + 3 * SUB_BYTES + so1, pB + KP + ko + 8);
            CP_COMMIT();
        }

        uint32_t stb = sb + s * STAGE_BYTES;
#pragma unroll
        for (int ks = 0; ks < 2; ks++) {
            uint32_t ao = stb + (aoff00 ^ (ks * 32));
            uint32_t bo = stb + (boff00 ^ (ks * 32));
            uint32_t ahi[2][4], alo[2][4], bfr[4][4];
            ldsm4(ahi[0], ao);
            ldsm4(ahi[1], ao + 1024);
            ldsm4(alo[0], ao + SUB_BYTES);
            ldsm4(alo[1], ao + SUB_BYTES + 1024);
#pragma unroll
            for (int g = 0; g < 4; g++) ldsm4(bfr[g], bo + g * 1024);
            // term1: hi*hi -> f32 acc
#pragma unroll
            for (int g = 0; g < 4; g++)
#pragma unroll
                for (int h = 0; h < 2; h++)
#pragma unroll
                    for (int mi = 0; mi < 2; mi++)
                        mma_f32acc(acc[mi][g * 2 + h], ahi[mi], bfr[g][h], bfr[g][h + 2]);
            // term2: lo*hi -> f16 acc
#pragma unroll
            for (int g = 0; g < 4; g++)
#pragma unroll
                for (int h = 0; h < 2; h++)
#pragma unroll
                    for (int mi = 0; mi < 2; mi++)
                        mma_f16acc(hacc[mi][g * 2 + h], alo[mi], bfr[g][h], bfr[g][h + 2]);
            // reload B regs with B-lo (WAR only)
#pragma unroll
            for (int g = 0; g < 4; g++) ldsm4(bfr[g], bo + SUB_BYTES + g * 1024);
            // term3: hi*lo -> f16 acc
#pragma unroll
            for (int g = 0; g < 4; g++)
#pragma unroll
                for (int h = 0; h < 2; h++)
#pragma unroll
                    for (int mi = 0; mi < 2; mi++)
                        mma_f16acc(hacc[mi][g * 2 + h], ahi[mi], bfr[g][h], bfr[g][h + 2]);
        }
        s++; if (s == STG) s = 0;
        sload++; if (sload == STG) sload = 0;
    }

    // epilogue: combine f32 + f16 accumulators
    int erow0 = gm * BM + warp_m * 32 + (lane >> 2);
    int ecol0 = gn * BN + warp_n * 64 + (lane & 3) * 2;
#pragma unroll
    for (int mi = 0; mi < 2; mi++) {
#pragma unroll
        for (int ni = 0; ni < 8; ni++) {
            float2 c01 = __half22float2(*reinterpret_cast<__half2*>(&hacc[mi][ni][0]));
            float2 c23 = __half22float2(*reinterpret_cast<__half2*>(&hacc[mi][ni][1]));
            float v[4];
            v[0] = acc[mi][ni][0] + c01.x;
            v[1] = acc[mi][ni][1] + c01.y;
            v[2] = acc[mi][ni][2] + c23.x;
            v[3] = acc[mi][ni][3] + c23.y;
            int r = erow0 + mi * 16;
            int cc = ecol0 + ni * 8;
#pragma unroll
            for (int half_i = 0; half_i < 2; half_i++) {
                int rr = r + half_i * 8;
                if (rr < M) {
                    float v0 = v[half_i * 2 + 0];
                    float v1 = v[half_i * 2 + 1];
                    if (cc < N) {
                        float o = v0;
                        if (flags & 1) o += bias[cc];
                        if (flags & 2) o = fmaxf(o, 0.f);
                        C[(size_t)rr * ldc + cc] = o;
                    }
                    if (cc + 1 < N) {
                        float o = v1;
                        if (flags & 1) o += bias[cc + 1];
                        if (flags & 2) o = fmaxf(o, 0.f);
                        C[(size_t)rr * ldc + cc + 1] = o;
                    }
                }
            }
        }
    }
}

// ---------------- conversion kernels (fp16 hi/lo) ----------------
__device__ __forceinline__ uint32_t pack_h2(__half a, __half b) {
    return ((uint32_t)__half_as_ushort(b) << 16) | __half_as_ushort(a);
}

__global__ void k_splitA2(const float* __restrict__ src, __half* __restrict__ dst,
                          int M, int K, int KP)
{
    int k = (blockIdx.x * 256 + threadIdx.x) * 4;
    int m = blockIdx.y;
    if (k >= KP) return;
    float4 v = make_float4(0.f, 0.f, 0.f, 0.f);
    if (m < M && k < K) v = *reinterpret_cast<const float4*>(&src[(size_t)m * K + k]);
    __half h0 = __float2half_rn(v.x), h1 = __float2half_rn(v.y);
    __half h2 = __float2half_rn(v.z), h3 = __float2half_rn(v.w);
    __half l0 = __float2half_rn(v.x - __half2float(h0));
    __half l1 = __float2half_rn(v.y - __half2float(h1));
    __half l2 = __float2half_rn(v.z - __half2float(h2));
    __half l3 = __float2half_rn(v.w - __half2float(h3));
    uint2 hp, lp;
    hp.x = pack_h2(h0, h1); hp.y = pack_h2(h2, h3);
    lp.x = pack_h2(l0, l1); lp.y = pack_h2(l2, l3);
    size_t base = (size_t)m * (2 * KP);
    *reinterpret_cast<uint2*>(&dst[base + k]) = hp;
    *reinterpret_cast<uint2*>(&dst[base + KP + k]) = lp;
}

__global__ void k_splitBT2(const float* __restrict__ src, __half* __restrict__ dst,
                           int K, int N, int KP)
{
    __shared__ float t[64][33];
    int k0 = blockIdx.x * 64, n0 = blockIdx.y * 32;
    int tx = threadIdx.x, ty = threadIdx.y;   // 32 x 8
#pragma unroll
    for (int it = 0; it < 8; it++) {
        int k = k0 + ty + it * 8;
        int n = n0 + tx;
        t[ty + it * 8][tx] = (k < K && n < N) ? src[(size_t)k * N + n] : 0.f;
    }
    __syncthreads();
    int uid = ty * 32 + tx;
    int nl = uid >> 3;
    int kg = (uid & 7) * 8;
    size_t base = (size_t)(n0 + nl) * (2 * KP) + k0;
#pragma unroll
    for (int q = 0; q < 4; q++) {
        int kk = kg + q * 2;
        float v0 = t[kk][nl], v1 = t[kk + 1][nl];
        __half h0 = __float2half_rn(v0), h1 = __float2half_rn(v1);
        __half l0 = __float2half_rn(v0 - __half2float(h0));
        __half l1 = __float2half_rn(v1 - __half2float(h1));
        *reinterpret_cast<uint32_t*>(&dst[base + kk]) = pack_h2(h0, h1);
        *reinterpret_cast<uint32_t*>(&dst[base + KP + kk]) = pack_h2(l0, l1);
    }
}

// ---------------- scalar SGEMM (tiny MLP tail layers) ----------------
__global__ __launch_bounds__(256) void sgemm(const float* __restrict__ A,
                                             const float* __restrict__ B,
                                             const float* __restrict__ bias,
                                             float* __restrict__ C,
                                             int M, int N, int K,
                                             int hasBias, int doRelu) {
    __shared__ float As[8][128];
    __shared__ float Bs[8][128];
    const int tid   = threadIdx.x;
    const int tileM = blockIdx.y * 128;
    const int tileN = blockIdx.x * 128;

    const int aRow = tid >> 1;
    const int aK4  = (tid & 1) * 4;
    const int bRow = tid >> 5;
    const int bCol = (tid & 31) * 4;
    const int ty   = tid >> 4;
    const int tx   = tid & 15;

    float acc[8][8];
#pragma unroll
    for (int i = 0; i < 8; i++)
#pragma unroll
        for (int j = 0; j < 8; j++) acc[i][j] = 0.f;

    for (int k0 = 0; k0 < K; k0 += 8) {
        float4 av = make_float4(0.f, 0.f, 0.f, 0.f);
        int gr = tileM + aRow;
        if (gr < M) av = *reinterpret_cast<const float4*>(&A[(size_t)gr * K + k0 + aK4]);
        As[aK4 + 0][aRow] = av.x;
        As[aK4 + 1][aRow] = av.y;
        As[aK4 + 2][aRow] = av.z;
        As[aK4 + 3][aRow] = av.w;

        float4 bv = make_float4(0.f, 0.f, 0.f, 0.f);
        int gc = tileN + bCol;
        const float* bp = &B[(size_t)(k0 + bRow) * N + gc];
        if (gc + 3 < N) {
            bv = *reinterpret_cast<const float4*>(bp);
        } else {
            if (gc + 0 < N) bv.x = bp[0];
            if (gc + 1 < N) bv.y = bp[1];
            if (gc + 2 < N) bv.z = bp[2];
            if (gc + 3 < N) bv.w = bp[3];
        }
        *reinterpret_cast<float4*>(&Bs[bRow][bCol]) = bv;

        __syncthreads();
#pragma unroll
        for (int kk = 0; kk < 8; kk++) {
            float a[8], b[8];
            *reinterpret_cast<float4*>(&a[0]) = *reinterpret_cast<float4*>(&As[kk][ty * 8]);
            *reinterpret_cast<float4*>(&a[4]) = *reinterpret_cast<float4*>(&As[kk][ty * 8 + 4]);
            *reinterpret_cast<float4*>(&b[0]) = *reinterpret_cast<float4*>(&Bs[kk][tx * 8]);
            *reinterpret_cast<float4*>(&b[4]) = *reinterpret_cast<float4*>(&Bs[kk][tx * 8 + 4]);
#pragma unroll
            for (int i = 0; i < 8; i++)
#pragma unroll
                for (int j = 0; j < 8; j++) acc[i][j] = fmaf(a[i], b[j], acc[i][j]);
        }
        __syncthreads();
    }

#pragma unroll
    for (int i = 0; i < 8; i++) {
        int row = tileM + ty * 8 + i;
        if (row >= M) continue;
#pragma unroll
        for (int j = 0; j < 8; j++) {
            int col = tileN + tx * 8 + j;
            if (col < N) {
                float v = acc[i][j];
                if (hasBias) v += bias[col];
                if (doRelu) v = fmaxf(v, 0.f);
                C[(size_t)row * N + col] = v;
            }
        }
    }
}

// ---------------- CSR build ----------------
__global__ void k_init() {
    int i = blockIdx.x * blockDim.x + threadIdx.x;
    if (i < NN) { g_cnt[i] = 0; g_cur[i] = 0; }
    if (i < GG) { g_pstart[i] = 0x7fffffff; g_pend[i] = -1; g_pcnt[i] = 0; }
}

__global__ void k_count(const int* __restrict__ ei) {
    int k = blockIdx.x * blockDim.x + threadIdx.x;
    if (k >= ETOT) return;
    int dst = (k < EE) ? ei[EE + k] : (k - EE);
    atomicAdd(&g_cnt[dst], 1);
}

__global__ __launch_bounds__(1024) void k_scan() {
    __shared__ int sd[1024];
    __shared__ int scarry;
    int tid = threadIdx.x;
    if (tid == 0) { scarry = 0; g_start[0] = 0; }
    __syncthreads();
    for (int base = 0; base < NN; base += 1024) {
        int v = (base + tid < NN) ? g_cnt[base + tid] : 0;
        sd[tid] = v;
        __syncthreads();
        for (int o = 1; o < 1024; o <<= 1) {
            int t = (tid >= o) ? sd[tid - o] : 0;
            __syncthreads();
            sd[tid] += t;
            __syncthreads();
        }
        int run = scarry;
        if (base + tid < NN) g_start[base + tid + 1] = run + sd[tid];
        __syncthreads();
        if (tid == 1023) scarry = run + sd[1023];
        __syncthreads();
    }
}

__global__ void k_scatter(const int* __restrict__ ei) {
    int k = blockIdx.x * blockDim.x + threadIdx.x;
    if (k >= ETOT) return;
    int src = (k < EE) ? ei[k]      : (k - EE);
    int dst = (k < EE) ? ei[EE + k] : (k - EE);
    int pos = g_start[dst] + atomicAdd(&g_cur[dst], 1);
    g_esrc[pos] = src;
}

__global__ void k_dinv() {
    int i = blockIdx.x * blockDim.x + threadIdx.x;
    if (i < NN) g_dinv[i] = rsqrtf((float)g_cnt[i]);
}

// ---------------- attention ----------------
__global__ void k_attn(const float* __restrict__ xh, const float* __restrict__ a_s,
                       const float* __restrict__ a_d) {
    int n = blockIdx.x;
    int w = threadIdx.x >> 5;
    int lane = threadIdx.x & 31;
    if (w >= HH) return;
    const float* row = xh + (size_t)n * HFD + w * FF;
    const float* as  = a_s + w * FF;
    const float* ad  = a_d + w * FF;
    float s1 = 0.f, s2 = 0.f;
    for (int f = lane; f < FF; f += 32) {
        float v = row[f];
        s1 = fmaf(v, as[f], s1);
        s2 = fmaf(v, ad[f], s2);
    }
#pragma unroll
    for (int o = 16; o; o >>= 1) {
        s1 += __shfl_down_sync(0xffffffffu, s1, o);
        s2 += __shfl_down_sync(0xffffffffu, s2, o);
    }
    if (lane == 0) { g_als[n * HH + w] = s1; g_ald[n * HH + w] = s2; }
}

__global__ void k_softmax() {
    int node = blockIdx.x * blockDim.y + threadIdx.y;
    if (node >= NN) return;
    int lane = threadIdx.x;
    bool act = lane < HH;
    int s = g_start[node], e = g_start[node + 1];
    float ald_v = act ? g_ald[node * HH + lane] : 0.f;
    float mx = -3.0e38f;
    for (int p = s; p < e; p++) {
        int src = g_esrc[p];
        if (act) {
            float v = g_als[src * HH + lane] + ald_v;
            v = fmaxf(v, 0.2f * v);
            mx = fmaxf(mx, v);
        }
    }
    float z = 0.f;
    for (int p = s; p < e; p++) {
        int src = g_esrc[p];
        if (act) {
            float v = g_als[src * HH + lane] + ald_v;
            v = fmaxf(v, 0.2f * v);
            float ex = expf(v - mx);
            g_alpha[(size_t)p * HH + lane] = ex;
            z += ex;
        }
    }
    float inv = 1.f / (z + 1e-16f);
    for (int p = s; p < e; p++)
        if (act) g_alpha[(size_t)p * HH + lane] *= inv;
}

// ---------------- GAT aggregation fused with A-panel split (grid = MP_G) ----------------
__global__ __launch_bounds__(256) void k_gat_agg_split(const float* __restrict__ bias) {
    int n = blockIdx.x, tid = threadIdx.x;
    __half* arow = s_a2 + (size_t)n * (2 * KP2);
    if (n >= NN) {
        for (int k = tid; k < 2 * KP2 / 2; k += 256)
            reinterpret_cast<uint32_t*>(arow)[k] = 0;
        return;
    }
    int s = g_start[n], e = g_start[n + 1];
    float2 acc[PCH];
    int hidx[PCH];
#pragma unroll
    for (int i = 0; i < PCH; i++) {
        int f = 2 * tid + 512 * i;
        hidx[i] = (f < HFD) ? (f / FF) : 0;
        acc[i].x = (f < HFD) ? bias[f] : 0.f;
        acc[i].y = (f + 1 < HFD) ? bias[f + 1] : 0.f;
    }
    for (int p = s; p < e; p++) {
        int src = g_esrc[p];
        const float2* xr = reinterpret_cast<const float2*>(g_xh + (size_t)src * HFD);
        const float* al = g_alpha + (size_t)p * HH;
#pragma unroll
        for (int i = 0; i < PCH; i++) {
            int f = 2 * tid + 512 * i;
            if (f < HFD) {
                float2 v = xr[f >> 1];
                float a = al[hidx[i]];
                acc[i].x = fmaf(a, v.x, acc[i].x);
                acc[i].y = fmaf(a, v.y, acc[i].y);
            }
        }
    }
#pragma unroll
    for (int i = 0; i < PCH; i++) {
        int f = 2 * tid + 512 * i;
        if (f < KP2) {
            float vx = (f < HFD) ? fmaxf(acc[i].x, 0.f) : 0.f;
            float vy = (f + 1 < HFD) ? fmaxf(acc[i].y, 0.f) : 0.f;
            __half hx = __float2half_rn(vx), hy = __float2half_rn(vy);
            __half lx = __float2half_rn(vx - __half2float(hx));
            __half ly = __float2half_rn(vy - __half2float(hy));
            *reinterpret_cast<uint32_t*>(&arow[f]) = pack_h2(hx, hy);
            *reinterpret_cast<uint32_t*>(&arow[KP2 + f]) = pack_h2(lx, ly);
        }
    }
}

// ---------------- GCN aggregation ----------------
#define FCH 27
__global__ __launch_bounds__(256) void k_gcn_agg(const float* __restrict__ bias) {
    int n = blockIdx.x, tid = threadIdx.x;
    int s = g_start[n], e = g_start[n + 1];
    float dv = g_dinv[n];
    float acc[FCH];
#pragma unroll
    for (int i = 0; i < FCH; i++) {
        int f = tid + i * 256;
        acc[i] = (f < HFD) ? bias[f] : 0.f;
    }
    for (int p = s; p < e; p++) {
        int src = g_esrc[p];
        float coef = g_dinv[src] * dv;
        const float* xr = g_xw + (size_t)src * HFD;
#pragma unroll
        for (int i = 0; i < FCH; i++) {
            int f = tid + i * 256;
            if (f < HFD) acc[i] = fmaf(coef, xr[f], acc[i]);
        }
    }
    float* o = g_h2 + (size_t)n * HFD;
#pragma unroll
    for (int i = 0; i < FCH; i++) {
        int f = tid + i * 256;
        if (f < HFD) o[f] = fmaxf(acc[i], 0.f);
    }
}

// ---------------- pooling fused with MLP1 A-panel split ----------------
__global__ void k_ranges(const int* __restrict__ batch) {
    int i = blockIdx.x * blockDim.x + threadIdx.x;
    if (i >= NN) return;
    int b = batch[i];
    if (b >= 0 && b < GG) {
        atomicMin(&g_pstart[b], i);
        atomicMax(&g_pend[b], i);
        atomicAdd(&g_pcnt[b], 1);
    }
}

__device__ __forceinline__ void h_split_store(__half* hi, __half* lo, float v) {
    __half h = __float2half_rn(v);
    *hi = h;
    *lo = __float2half_rn(v - __half2float(h));
}

__global__ __launch_bounds__(256) void k_pool_split() {
    int g = blockIdx.y;
    int f = blockIdx.x * blockDim.x + threadIdx.x;
    if (f >= HFD) return;
    int s = g_pstart[g], e = g_pend[g];
    float mx = -3.0e38f, sm = 0.f;
    for (int n = s; n <= e; n++) {
        float v = g_h2[(size_t)n * HFD + f];
        mx = fmaxf(mx, v);
        sm += v;
    }
    float gap = sm / (float)g_pcnt[g];
    __half* row = s_a2 + (size_t)g * (2 * KPM);
    h_split_store(&row[f],       &row[KPM + f],       mx);
    h_split_store(&row[HFD + f], &row[KPM + HFD + f], gap);
}

__global__ void k_pool_pad() {
    int g = blockIdx.x;
    int t = threadIdx.x;
    __half* row = s_a2 + (size_t)g * (2 * KPM);
    row[HF2 + t] = __float2half_rn(0.f);
    row[KPM + HF2 + t] = __float2half_rn(0.f);
}

// ---------------- launch ----------------
extern "C" void kernel_launch(void* const* d_in, const int* in_sizes, int n_in,
                              void* d_out, int out_size) {
    const float* x     = (const float*)d_in[0];
    const int*   ei    = (const int*)  d_in[1];
    const int*   batch = (const int*)  d_in[2];
    const float* W_gat = (const float*)d_in[3];
    const float* a_src = (const float*)d_in[4];
    const float* a_dst = (const float*)d_in[5];
    const float* b_gat = (const float*)d_in[6];
    const float* W_gcn = (const float*)d_in[7];
    const float* b_gcn = (const float*)d_in[8];
    const float* W1    = (const float*)d_in[9];
    const float* b1    = (const float*)d_in[10];
    const float* W2    = (const float*)d_in[11];
    const float* b2    = (const float*)d_in[12];
    const float* W3    = (const float*)d_in[13];
    const float* b3    = (const float*)d_in[14];
    float* out = (float*)d_out;

    float *p_xh, *p_xw, *p_m1, *p_m2;
    __half *p_a2, *p_b2;
    cudaGetSymbolAddress((void**)&p_xh,   g_xh);
    cudaGetSymbolAddress((void**)&p_xw,   g_xw);
    cudaGetSymbolAddress((void**)&p_m1,   g_mlp1);
    cudaGetSymbolAddress((void**)&p_m2,   g_mlp2);
    cudaGetSymbolAddress((void**)&p_a2,   s_a2);
    cudaGetSymbolAddress((void**)&p_b2,   s_b2);

    cudaFuncSetAttribute(mma_gemm, cudaFuncAttributeMaxDynamicSharedMemorySize, SMEM_MMA);

    const int TM = MP_G / 128;   // 63
    const int TN = NPAD / 128;   // 54

    // ---- GEMM1 split first; mma_gemm lands at launch index 3 (ncu capture slot) ----
    {
        dim3 gA((KP1 / 4 + 255) / 256, MP_G);
        k_splitA2<<<gA, 256>>>(x, p_a2, NN, FF, KP1);                 // 0
        dim3 gB(KP1 / 64, NPAD / 32);
        k_splitBT2<<<gB, dim3(32, 8)>>>(W_gat, p_b2, FF, HFD, KP1);   // 1
    }
    k_init<<<(NN + 255) / 256, 256>>>();                               // 2
    mma_gemm<<<TM * TN, 256, SMEM_MMA>>>(p_a2, p_b2, nullptr, p_xh,    // 3 <- profiled
                                         NN, HFD, HFD, KP1, TM, TN, 0);

    // CSR build + degrees
    k_count<<<(ETOT + 255) / 256, 256>>>(ei);
    k_scan<<<1, 1024>>>();
    k_scatter<<<(ETOT + 255) / 256, 256>>>(ei);
    k_dinv<<<(NN + 255) / 256, 256>>>();

    k_attn<<<NN, 320>>>(p_xh, a_src, a_dst);
    k_softmax<<<(NN + 7) / 8, dim3(32, 8)>>>();
    k_gat_agg_split<<<MP_G, 256>>>(b_gat);

    // ---- GEMM2: xw = h @ W_gcn ----
    {
        dim3 gB(KP2 / 64, NPAD / 32);
        k_splitBT2<<<gB, dim3(32, 8)>>>(W_gcn, p_b2, HFD, HFD, KP2);
        mma_gemm<<<TM * TN, 256, SMEM_MMA>>>(p_a2, p_b2, nullptr, p_xw,
                                             NN, HFD, HFD, KP2, TM, TN, 0);
    }

    k_gcn_agg<<<NN, 256>>>(b_gcn);

    // pooling (writes MLP1 A-panel directly)
    k_ranges<<<(NN + 255) / 256, 256>>>(batch);
    {
        dim3 grid((HFD + 255) / 256, GG);
        k_pool_split<<<grid, 256>>>();
        k_pool_pad<<<GG, 32>>>();
    }

    // ---- MLP1: relu(pool @ W1 + b1) ----
    {
        dim3 gB(KPM / 64, 512 / 32);
        k_splitBT2<<<gB, dim3(32, 8)>>>(W1, p_b2, HF2, 512, KPM);
        mma_gemm<<<2 * 4, 256, SMEM_MMA>>>(p_a2, p_b2, b1, p_m1,
                                           GG, 512, 512, KPM, 2, 4, 3);
    }

    // MLP tail (tiny)
    {
        dim3 grid(1, 2);
        sgemm<<<grid, 256>>>(p_m1, W2, b2, p_m2, GG, 128, 512, 1, 0);
    }
    {
        dim3 grid(1, 2);
        sgemm<<<grid, 256>>>(p_m2, W3, b3, out, GG, 64, 128, 1, 0);
    }
}

// round 10
// speedup vs baseline: 1.5130x; 1.5130x over previous
#include <cuda_runtime.h>
#include <cuda_fp16.h>
#include <cstdint>
#include <cstddef>

// ---------------- problem constants (fixed shapes) ----------------
#define NN    8000
#define EE    32000
#define ETOT  40000
#define GG    256
#define FF    680
#define HH    10
#define HFD   6800
#define HF2   13600

#define MP_G  8064
#define KP1   704
#define KP2   6848
#define KPM   13632
#define NPAD  6912

#define PCH   14

// ---------------- scratch ----------------
__device__ float g_xh [(size_t)NN * HFD];
__device__ float g_xw [(size_t)NN * HFD];
__device__ float g_h2 [(size_t)NN * HFD];
__device__ float g_als[NN * HH];
__device__ float g_ald[NN * HH];
__device__ float g_alpha[(size_t)ETOT * HH];
__device__ int   g_cnt[NN];
__device__ int   g_cur[NN];
__device__ int   g_start[NN + 1];
__device__ int   g_esrc[ETOT];
__device__ float g_dinv[NN];
__device__ int   g_pstart[GG];
__device__ int   g_pend[GG];
__device__ int   g_pcnt[GG];
__device__ float g_mlp1[GG * 512];
__device__ float g_mlp2[GG * 128];

// fp16 panels: A=[hi|lo] (2KP per row), Bt = hi only (KP per row)
__device__ __half s_a2[(size_t)MP_G * (2 * KP2)];
__device__ __half s_b2[(size_t)NPAD * (2 * KP2)];   // oversized; only [NPAD, KP] used

// ---------------- PTX helpers ----------------
__device__ __forceinline__ uint32_t smem_u32(const void* p) {
    uint32_t a;
    asm("{ .reg .u64 t; cvta.to.shared.u64 t, %1; cvt.u32.u64 %0, t; }" : "=r"(a) : "l"(p));
    return a;
}

__device__ __forceinline__ void cp16(uint32_t dst, const void* src) {
    asm volatile("cp.async.cg.shared.global [%0], [%1], 16;" :: "r"(dst), "l"(src));
}
#define CP_COMMIT() asm volatile("cp.async.commit_group;" ::: "memory")
__device__ __forceinline__ void cp_wait(int pend) {
    if (pend <= 0)      asm volatile("cp.async.wait_group 0;" ::: "memory");
    else                asm volatile("cp.async.wait_group 1;" ::: "memory");
}

__device__ __forceinline__ void ldsm4(uint32_t* r, uint32_t addr) {
    asm volatile("ldmatrix.sync.aligned.m8n8.x4.shared.b16 {%0,%1,%2,%3}, [%4];"
                 : "=r"(r[0]), "=r"(r[1]), "=r"(r[2]), "=r"(r[3]) : "r"(addr));
}

__device__ __forceinline__ void mma_f32acc(float* d, const uint32_t* a, uint32_t b0, uint32_t b1) {
    asm volatile("mma.sync.aligned.m16n8k16.row.col.f32.f16.f16.f32 "
                 "{%0,%1,%2,%3}, {%4,%5,%6,%7}, {%8,%9}, {%0,%1,%2,%3};"
                 : "+f"(d[0]), "+f"(d[1]), "+f"(d[2]), "+f"(d[3])
                 : "r"(a[0]), "r"(a[1]), "r"(a[2]), "r"(a[3]), "r"(b0), "r"(b1));
}

__device__ __forceinline__ uint32_t sm_tile_off(int row, int chunk) {
    return (uint32_t)(row * 64 + ((chunk ^ ((row >> 1) & 3)) << 4));
}

// ---------------- fp16 2-term GEMM: (A_hi + A_lo) * B_hi, fp32 accum ----------------
// Stage = [Ahi 8K][Alo 8K][Bhi 8K] = 24KB, 3 stages.
#define BM 128
#define BN 128
#define BK 32
#define STG 3
#define SUB_BYTES   8192
#define STAGE_BYTES 24576
#define SMEM_MMA (STG * STAGE_BYTES)

__global__ __launch_bounds__(256, 2) void mma_gemm(
    const __half* __restrict__ A2, const __half* __restrict__ B2,
    const float* __restrict__ bias, float* __restrict__ C,
    int M, int N, int ldc, int KP, int tiles_m, int tiles_n, int flags)
{
    extern __shared__ char smem[];
    uint32_t sb = smem_u32(smem);
    const int tid = threadIdx.x;
    const int wid = tid >> 5;
    const int lane = tid & 31;
    const int warp_m = wid & 3;
    const int warp_n = wid >> 2;

    int gm, gn;
    {
        const int GM = 8;
        int bid = blockIdx.x;
        int per = GM * tiles_n;
        int grp = bid / per;
        int fm  = grp * GM;
        int gsz = tiles_m - fm; if (gsz > GM) gsz = GM;
        int r = bid - grp * per;
        gm = fm + r % gsz;
        gn = r / gsz;
    }

    const int CH = KP / BK;
    const int KA2 = 2 * KP;   // A panel row stride (hi|lo)

    const int lrow = tid >> 1;
    const int lc0  = (tid & 1) * 2;
    const __half* pA = A2 + (size_t)(gm * BM + lrow) * KA2 + lc0 * 8;
    const __half* pB = B2 + (size_t)(gn * BN + lrow) * KP  + lc0 * 8;   // hi-only panel
    const uint32_t so0 = sm_tile_off(lrow, lc0);
    const uint32_t so1 = so0 ^ 16;

    const uint32_t aoff00 = sm_tile_off(warp_m * 32 + (lane & 15), (lane >> 4));
    const uint32_t boff00 = 2 * SUB_BYTES + sm_tile_off(warp_n * 64 + (lane & 15), (lane >> 4));

    float acc[2][8][4];
#pragma unroll
    for (int mi = 0; mi < 2; mi++)
#pragma unroll
        for (int ni = 0; ni < 8; ni++)
#pragma unroll
            for (int j = 0; j < 4; j++) acc[mi][ni][j] = 0.f;

    // preload chunks 0,1
#pragma unroll
    for (int c = 0; c < 2 && c < CH; c++) {
        uint32_t stb = sb + c * STAGE_BYTES;
        int ko = c * BK;
        cp16(stb + so0,                 pA + ko);
        cp16(stb + so1,                 pA + ko + 8);
        cp16(stb + SUB_BYTES + so0,     pA + KP + ko);
        cp16(stb + SUB_BYTES + so1,     pA + KP + ko + 8);
        cp16(stb + 2 * SUB_BYTES + so0, pB + ko);
        cp16(stb + 2 * SUB_BYTES + so1, pB + ko + 8);
        CP_COMMIT();
    }

    int s = 0;
    int sload = 2;
    for (int c = 0; c < CH; c++) {
        cp_wait((CH - 1 - c) >= 1 ? 1 : 0);
        __syncthreads();

        if (c + 2 < CH) {
            uint32_t dtb = sb + sload * STAGE_BYTES;
            int ko = (c + 2) * BK;
            cp16(dtb + so0,                 pA + ko);
            cp16(dtb + so1,                 pA + ko + 8);
            cp16(dtb + SUB_BYTES + so0,     pA + KP + ko);
            cp16(dtb + SUB_BYTES + so1,     pA + KP + ko + 8);
            cp16(dtb + 2 * SUB_BYTES + so0, pB + ko);
            cp16(dtb + 2 * SUB_BYTES + so1, pB + ko + 8);
            CP_COMMIT();
        }

        uint32_t stb = sb + s * STAGE_BYTES;
#pragma unroll
        for (int ks = 0; ks < 2; ks++) {
            uint32_t ao = stb + (aoff00 ^ (ks * 32));
            uint32_t bo = stb + (boff00 ^ (ks * 32));
            uint32_t ahi[2][4], alo[2][4], bfr[4][4];
            ldsm4(ahi[0], ao);
            ldsm4(ahi[1], ao + 1024);
            ldsm4(alo[0], ao + SUB_BYTES);
            ldsm4(alo[1], ao + SUB_BYTES + 1024);
#pragma unroll
            for (int g = 0; g < 4; g++) ldsm4(bfr[g], bo + g * 1024);
            // pass1: hi*hi
#pragma unroll
            for (int g = 0; g < 4; g++)
#pragma unroll
                for (int h = 0; h < 2; h++)
#pragma unroll
                    for (int mi = 0; mi < 2; mi++)
                        mma_f32acc(acc[mi][g * 2 + h], ahi[mi], bfr[g][h], bfr[g][h + 2]);
            // pass2: lo*hi
#pragma unroll
            for (int g = 0; g < 4; g++)
#pragma unroll
                for (int h = 0; h < 2; h++)
#pragma unroll
                    for (int mi = 0; mi < 2; mi++)
                        mma_f32acc(acc[mi][g * 2 + h], alo[mi], bfr[g][h], bfr[g][h + 2]);
        }
        s++; if (s == STG) s = 0;
        sload++; if (sload == STG) sload = 0;
    }

    // epilogue
    int erow0 = gm * BM + warp_m * 32 + (lane >> 2);
    int ecol0 = gn * BN + warp_n * 64 + (lane & 3) * 2;
#pragma unroll
    for (int mi = 0; mi < 2; mi++) {
#pragma unroll
        for (int ni = 0; ni < 8; ni++) {
            int r = erow0 + mi * 16;
            int cc = ecol0 + ni * 8;
#pragma unroll
            for (int half_i = 0; half_i < 2; half_i++) {
                int rr = r + half_i * 8;
                if (rr < M) {
                    float v0 = acc[mi][ni][half_i * 2 + 0];
                    float v1 = acc[mi][ni][half_i * 2 + 1];
                    if (cc < N) {
                        float o = v0;
                        if (flags & 1) o += bias[cc];
                        if (flags & 2) o = fmaxf(o, 0.f);
                        C[(size_t)rr * ldc + cc] = o;
                    }
                    if (cc + 1 < N) {
                        float o = v1;
                        if (flags & 1) o += bias[cc + 1];
                        if (flags & 2) o = fmaxf(o, 0.f);
                        C[(size_t)rr * ldc + cc + 1] = o;
                    }
                }
            }
        }
    }
}

// ---------------- conversion kernels ----------------
__device__ __forceinline__ uint32_t pack_h2(__half a, __half b) {
    return ((uint32_t)__half_as_ushort(b) << 16) | __half_as_ushort(a);
}

// A[M,K] fp32 -> [Mp, 2KP] fp16 hi|lo
__global__ void k_splitA2(const float* __restrict__ src, __half* __restrict__ dst,
                          int M, int K, int KP)
{
    int k = (blockIdx.x * 256 + threadIdx.x) * 4;
    int m = blockIdx.y;
    if (k >= KP) return;
    float4 v = make_float4(0.f, 0.f, 0.f, 0.f);
    if (m < M && k < K) v = *reinterpret_cast<const float4*>(&src[(size_t)m * K + k]);
    __half h0 = __float2half_rn(v.x), h1 = __float2half_rn(v.y);
    __half h2 = __float2half_rn(v.z), h3 = __float2half_rn(v.w);
    __half l0 = __float2half_rn(v.x - __half2float(h0));
    __half l1 = __float2half_rn(v.y - __half2float(h1));
    __half l2 = __float2half_rn(v.z - __half2float(h2));
    __half l3 = __float2half_rn(v.w - __half2float(h3));
    uint2 hp, lp;
    hp.x = pack_h2(h0, h1); hp.y = pack_h2(h2, h3);
    lp.x = pack_h2(l0, l1); lp.y = pack_h2(l2, l3);
    size_t base = (size_t)m * (2 * KP);
    *reinterpret_cast<uint2*>(&dst[base + k]) = hp;
    *reinterpret_cast<uint2*>(&dst[base + KP + k]) = lp;
}

// B[K,N] fp32 -> transposed [Np, KP] fp16 hi only
__global__ void k_splitBT2(const float* __restrict__ src, __half* __restrict__ dst,
                           int K, int N, int KP)
{
    __shared__ float t[64][33];
    int k0 = blockIdx.x * 64, n0 = blockIdx.y * 32;
    int tx = threadIdx.x, ty = threadIdx.y;   // 32 x 8
#pragma unroll
    for (int it = 0; it < 8; it++) {
        int k = k0 + ty + it * 8;
        int n = n0 + tx;
        t[ty + it * 8][tx] = (k < K && n < N) ? src[(size_t)k * N + n] : 0.f;
    }
    __syncthreads();
    int uid = ty * 32 + tx;
    int nl = uid >> 3;
    int kg = (uid & 7) * 8;
    size_t base = (size_t)(n0 + nl) * KP + k0;
#pragma unroll
    for (int q = 0; q < 4; q++) {
        int kk = kg + q * 2;
        float v0 = t[kk][nl], v1 = t[kk + 1][nl];
        *reinterpret_cast<uint32_t*>(&dst[base + kk]) =
            pack_h2(__float2half_rn(v0), __float2half_rn(v1));
    }
}

// ---------------- scalar SGEMM (tiny MLP tail layers) ----------------
__global__ __launch_bounds__(256) void sgemm(const float* __restrict__ A,
                                             const float* __restrict__ B,
                                             const float* __restrict__ bias,
                                             float* __restrict__ C,
                                             int M, int N, int K,
                                             int hasBias, int doRelu) {
    __shared__ float As[8][128];
    __shared__ float Bs[8][128];
    const int tid   = threadIdx.x;
    const int tileM = blockIdx.y * 128;
    const int tileN = blockIdx.x * 128;

    const int aRow = tid >> 1;
    const int aK4  = (tid & 1) * 4;
    const int bRow = tid >> 5;
    const int bCol = (tid & 31) * 4;
    const int ty   = tid >> 4;
    const int tx   = tid & 15;

    float acc[8][8];
#pragma unroll
    for (int i = 0; i < 8; i++)
#pragma unroll
        for (int j = 0; j < 8; j++) acc[i][j] = 0.f;

    for (int k0 = 0; k0 < K; k0 += 8) {
        float4 av = make_float4(0.f, 0.f, 0.f, 0.f);
        int gr = tileM + aRow;
        if (gr < M) av = *reinterpret_cast<const float4*>(&A[(size_t)gr * K + k0 + aK4]);
        As[aK4 + 0][aRow] = av.x;
        As[aK4 + 1][aRow] = av.y;
        As[aK4 + 2][aRow] = av.z;
        As[aK4 + 3][aRow] = av.w;

        float4 bv = make_float4(0.f, 0.f, 0.f, 0.f);
        int gc = tileN + bCol;
        const float* bp = &B[(size_t)(k0 + bRow) * N + gc];
        if (gc + 3 < N) {
            bv = *reinterpret_cast<const float4*>(bp);
        } else {
            if (gc + 0 < N) bv.x = bp[0];
            if (gc + 1 < N) bv.y = bp[1];
            if (gc + 2 < N) bv.z = bp[2];
            if (gc + 3 < N) bv.w = bp[3];
        }
        *reinterpret_cast<float4*>(&Bs[bRow][bCol]) = bv;

        __syncthreads();
#pragma unroll
        for (int kk = 0; kk < 8; kk++) {
            float a[8], b[8];
            *reinterpret_cast<float4*>(&a[0]) = *reinterpret_cast<float4*>(&As[kk][ty * 8]);
            *reinterpret_cast<float4*>(&a[4]) = *reinterpret_cast<float4*>(&As[kk][ty * 8 + 4]);
            *reinterpret_cast<float4*>(&b[0]) = *reinterpret_cast<float4*>(&Bs[kk][tx * 8]);
            *reinterpret_cast<float4*>(&b[4]) = *reinterpret_cast<float4*>(&Bs[kk][tx * 8 + 4]);
#pragma unroll
            for (int i = 0; i < 8; i++)
#pragma unroll
                for (int j = 0; j < 8; j++) acc[i][j] = fmaf(a[i], b[j], acc[i][j]);
        }
        __syncthreads();
    }

#pragma unroll
    for (int i = 0; i < 8; i++) {
        int row = tileM + ty * 8 + i;
        if (row >= M) continue;
#pragma unroll
        for (int j = 0; j < 8; j++) {
            int col = tileN + tx * 8 + j;
            if (col < N) {
                float v = acc[i][j];
                if (hasBias) v += bias[col];
                if (doRelu) v = fmaxf(v, 0.f);
                C[(size_t)row * N + col] = v;
            }
        }
    }
}

// ---------------- CSR build ----------------
__global__ void k_init() {
    int i = blockIdx.x * blockDim.x + threadIdx.x;
    if (i < NN) { g_cnt[i] = 0; g_cur[i] = 0; }
    if (i < GG) { g_pstart[i] = 0x7fffffff; g_pend[i] = -1; g_pcnt[i] = 0; }
}

__global__ void k_count(const int* __restrict__ ei) {
    int k = blockIdx.x * blockDim.x + threadIdx.x;
    if (k >= ETOT) return;
    int dst = (k < EE) ? ei[EE + k] : (k - EE);
    atomicAdd(&g_cnt[dst], 1);
}

__global__ __launch_bounds__(1024) void k_scan() {
    __shared__ int sd[1024];
    __shared__ int scarry;
    int tid = threadIdx.x;
    if (tid == 0) { scarry = 0; g_start[0] = 0; }
    __syncthreads();
    for (int base = 0; base < NN; base += 1024) {
        int v = (base + tid < NN) ? g_cnt[base + tid] : 0;
        sd[tid] = v;
        __syncthreads();
        for (int o = 1; o < 1024; o <<= 1) {
            int t = (tid >= o) ? sd[tid - o] : 0;
            __syncthreads();
            sd[tid] += t;
            __syncthreads();
        }
        int run = scarry;
        if (base + tid < NN) g_start[base + tid + 1] = run + sd[tid];
        __syncthreads();
        if (tid == 1023) scarry = run + sd[1023];
        __syncthreads();
    }
}

__global__ void k_scatter(const int* __restrict__ ei) {
    int k = blockIdx.x * blockDim.x + threadIdx.x;
    if (k >= ETOT) return;
    int src = (k < EE) ? ei[k]      : (k - EE);
    int dst = (k < EE) ? ei[EE + k] : (k - EE);
    int pos = g_start[dst] + atomicAdd(&g_cur[dst], 1);
    g_esrc[pos] = src;
}

__global__ void k_dinv() {
    int i = blockIdx.x * blockDim.x + threadIdx.x;
    if (i < NN) g_dinv[i] = rsqrtf((float)g_cnt[i]);
}

// ---------------- attention ----------------
__global__ void k_attn(const float* __restrict__ xh, const float* __restrict__ a_s,
                       const float* __restrict__ a_d) {
    int n = blockIdx.x;
    int w = threadIdx.x >> 5;
    int lane = threadIdx.x & 31;
    if (w >= HH) return;
    const float* row = xh + (size_t)n * HFD + w * FF;
    const float* as  = a_s + w * FF;
    const float* ad  = a_d + w * FF;
    float s1 = 0.f, s2 = 0.f;
    for (int f = lane; f < FF; f += 32) {
        float v = row[f];
        s1 = fmaf(v, as[f], s1);
        s2 = fmaf(v, ad[f], s2);
    }
#pragma unroll
    for (int o = 16; o; o >>= 1) {
        s1 += __shfl_down_sync(0xffffffffu, s1, o);
        s2 += __shfl_down_sync(0xffffffffu, s2, o);
    }
    if (lane == 0) { g_als[n * HH + w] = s1; g_ald[n * HH + w] = s2; }
}

__global__ void k_softmax() {
    int node = blockIdx.x * blockDim.y + threadIdx.y;
    if (node >= NN) return;
    int lane = threadIdx.x;
    bool act = lane < HH;
    int s = g_start[node], e = g_start[node + 1];
    float ald_v = act ? g_ald[node * HH + lane] : 0.f;
    float mx = -3.0e38f;
    for (int p = s; p < e; p++) {
        int src = g_esrc[p];
        if (act) {
            float v = g_als[src * HH + lane] + ald_v;
            v = fmaxf(v, 0.2f * v);
            mx = fmaxf(mx, v);
        }
    }
    float z = 0.f;
    for (int p = s; p < e; p++) {
        int src = g_esrc[p];
        if (act) {
            float v = g_als[src * HH + lane] + ald_v;
            v = fmaxf(v, 0.2f * v);
            float ex = expf(v - mx);
            g_alpha[(size_t)p * HH + lane] = ex;
            z += ex;
        }
    }
    float inv = 1.f / (z + 1e-16f);
    for (int p = s; p < e; p++)
        if (act) g_alpha[(size_t)p * HH + lane] *= inv;
}

// ---------------- GAT aggregation fused with A-panel split (grid = MP_G) ----------------
__global__ __launch_bounds__(256) void k_gat_agg_split(const float* __restrict__ bias) {
    int n = blockIdx.x, tid = threadIdx.x;
    __half* arow = s_a2 + (size_t)n * (2 * KP2);
    if (n >= NN) {
        for (int k = tid; k < 2 * KP2 / 2; k += 256)
            reinterpret_cast<uint32_t*>(arow)[k] = 0;
        return;
    }
    int s = g_start[n], e = g_start[n + 1];
    float2 acc[PCH];
    int hidx[PCH];
#pragma unroll
    for (int i = 0; i < PCH; i++) {
        int f = 2 * tid + 512 * i;
        hidx[i] = (f < HFD) ? (f / FF) : 0;
        acc[i].x = (f < HFD) ? bias[f] : 0.f;
        acc[i].y = (f + 1 < HFD) ? bias[f + 1] : 0.f;
    }
    for (int p = s; p < e; p++) {
        int src = g_esrc[p];
        const float2* xr = reinterpret_cast<const float2*>(g_xh + (size_t)src * HFD);
        const float* al = g_alpha + (size_t)p * HH;
#pragma unroll
        for (int i = 0; i < PCH; i++) {
            int f = 2 * tid + 512 * i;
            if (f < HFD) {
                float2 v = xr[f >> 1];
                float a = al[hidx[i]];
                acc[i].x = fmaf(a, v.x, acc[i].x);
                acc[i].y = fmaf(a, v.y, acc[i].y);
            }
        }
    }
#pragma unroll
    for (int i = 0; i < PCH; i++) {
        int f = 2 * tid + 512 * i;
        if (f < KP2) {
            float vx = (f < HFD) ? fmaxf(acc[i].x, 0.f) : 0.f;
            float vy = (f + 1 < HFD) ? fmaxf(acc[i].y, 0.f) : 0.f;
            __half hx = __float2half_rn(vx), hy = __float2half_rn(vy);
            __half lx = __float2half_rn(vx - __half2float(hx));
            __half ly = __float2half_rn(vy - __half2float(hy));
            *reinterpret_cast<uint32_t*>(&arow[f]) = pack_h2(hx, hy);
            *reinterpret_cast<uint32_t*>(&arow[KP2 + f]) = pack_h2(lx, ly);
        }
    }
}

// ---------------- GCN aggregation ----------------
#define FCH 27
__global__ __launch_bounds__(256) void k_gcn_agg(const float* __restrict__ bias) {
    int n = blockIdx.x, tid = threadIdx.x;
    int s = g_start[n], e = g_start[n + 1];
    float dv = g_dinv[n];
    float acc[FCH];
#pragma unroll
    for (int i = 0; i < FCH; i++) {
        int f = tid + i * 256;
        acc[i] = (f < HFD) ? bias[f] : 0.f;
    }
    for (int p = s; p < e; p++) {
        int src = g_esrc[p];
        float coef = g_dinv[src] * dv;
        const float* xr = g_xw + (size_t)src * HFD;
#pragma unroll
        for (int i = 0; i < FCH; i++) {
            int f = tid + i * 256;
            if (f < HFD) acc[i] = fmaf(coef, xr[f], acc[i]);
        }
    }
    float* o = g_h2 + (size_t)n * HFD;
#pragma unroll
    for (int i = 0; i < FCH; i++) {
        int f = tid + i * 256;
        if (f < HFD) o[f] = fmaxf(acc[i], 0.f);
    }
}

// ---------------- pooling fused with MLP1 A-panel split ----------------
__global__ void k_ranges(const int* __restrict__ batch) {
    int i = blockIdx.x * blockDim.x + threadIdx.x;
    if (i >= NN) return;
    int b = batch[i];
    if (b >= 0 && b < GG) {
        atomicMin(&g_pstart[b], i);
        atomicMax(&g_pend[b], i);
        atomicAdd(&g_pcnt[b], 1);
    }
}

__device__ __forceinline__ void h_split_store(__half* hi, __half* lo, float v) {
    __half h = __float2half_rn(v);
    *hi = h;
    *lo = __float2half_rn(v - __half2float(h));
}

__global__ __launch_bounds__(256) void k_pool_split() {
    int g = blockIdx.y;
    int f = blockIdx.x * blockDim.x + threadIdx.x;
    if (f >= HFD) return;
    int s = g_pstart[g], e = g_pend[g];
    float mx = -3.0e38f, sm = 0.f;
    for (int n = s; n <= e; n++) {
        float v = g_h2[(size_t)n * HFD + f];
        mx = fmaxf(mx, v);
        sm += v;
    }
    float gap = sm / (float)g_pcnt[g];
    __half* row = s_a2 + (size_t)g * (2 * KPM);
    h_split_store(&row[f],       &row[KPM + f],       mx);
    h_split_store(&row[HFD + f], &row[KPM + HFD + f], gap);
}

__global__ void k_pool_pad() {
    int g = blockIdx.x;
    int t = threadIdx.x;
    __half* row = s_a2 + (size_t)g * (2 * KPM);
    row[HF2 + t] = __float2half_rn(0.f);
    row[KPM + HF2 + t] = __float2half_rn(0.f);
}

// ---------------- launch ----------------
extern "C" void kernel_launch(void* const* d_in, const int* in_sizes, int n_in,
                              void* d_out, int out_size) {
    const float* x     = (const float*)d_in[0];
    const int*   ei    = (const int*)  d_in[1];
    const int*   batch = (const int*)  d_in[2];
    const float* W_gat = (const float*)d_in[3];
    const float* a_src = (const float*)d_in[4];
    const float* a_dst = (const float*)d_in[5];
    const float* b_gat = (const float*)d_in[6];
    const float* W_gcn = (const float*)d_in[7];
    const float* b_gcn = (const float*)d_in[8];
    const float* W1    = (const float*)d_in[9];
    const float* b1    = (const float*)d_in[10];
    const float* W2    = (const float*)d_in[11];
    const float* b2    = (const float*)d_in[12];
    const float* W3    = (const float*)d_in[13];
    const float* b3    = (const float*)d_in[14];
    float* out = (float*)d_out;

    float *p_xh, *p_xw, *p_m1, *p_m2;
    __half *p_a2, *p_b2;
    cudaGetSymbolAddress((void**)&p_xh,   g_xh);
    cudaGetSymbolAddress((void**)&p_xw,   g_xw);
    cudaGetSymbolAddress((void**)&p_m1,   g_mlp1);
    cudaGetSymbolAddress((void**)&p_m2,   g_mlp2);
    cudaGetSymbolAddress((void**)&p_a2,   s_a2);
    cudaGetSymbolAddress((void**)&p_b2,   s_b2);

    cudaFuncSetAttribute(mma_gemm, cudaFuncAttributeMaxDynamicSharedMemorySize, SMEM_MMA);

    const int TM = MP_G / 128;   // 63
    const int TN = NPAD / 128;   // 54

    // ---- GEMM1 split first; mma_gemm lands at launch index 3 (ncu capture slot) ----
    {
        dim3 gA((KP1 / 4 + 255) / 256, MP_G);
        k_splitA2<<<gA, 256>>>(x, p_a2, NN, FF, KP1);                 // 0
        dim3 gB(KP1 / 64, NPAD / 32);
        k_splitBT2<<<gB, dim3(32, 8)>>>(W_gat, p_b2, FF, HFD, KP1);   // 1
    }
    k_init<<<(NN + 255) / 256, 256>>>();                               // 2
    mma_gemm<<<TM * TN, 256, SMEM_MMA>>>(p_a2, p_b2, nullptr, p_xh,    // 3 <- profiled
                                         NN, HFD, HFD, KP1, TM, TN, 0);

    // CSR build + degrees
    k_count<<<(ETOT + 255) / 256, 256>>>(ei);
    k_scan<<<1, 1024>>>();
    k_scatter<<<(ETOT + 255) / 256, 256>>>(ei);
    k_dinv<<<(NN + 255) / 256, 256>>>();

    k_attn<<<NN, 320>>>(p_xh, a_src, a_dst);
    k_softmax<<<(NN + 7) / 8, dim3(32, 8)>>>();
    k_gat_agg_split<<<MP_G, 256>>>(b_gat);

    // ---- GEMM2: xw = h @ W_gcn ----
    {
        dim3 gB(KP2 / 64, NPAD / 32);
        k_splitBT2<<<gB, dim3(32, 8)>>>(W_gcn, p_b2, HFD, HFD, KP2);
        mma_gemm<<<TM * TN, 256, SMEM_MMA>>>(p_a2, p_b2, nullptr, p_xw,
                                             NN, HFD, HFD, KP2, TM, TN, 0);
    }

    k_gcn_agg<<<NN, 256>>>(b_gcn);

    // pooling (writes MLP1 A-panel directly)
    k_ranges<<<(NN + 255) / 256, 256>>>(batch);
    {
        dim3 grid((HFD + 255) / 256, GG);
        k_pool_split<<<grid, 256>>>();
        k_pool_pad<<<GG, 32>>>();
    }

    // ---- MLP1: relu(pool @ W1 + b1) ----
    {
        dim3 gB(KPM / 64, 512 / 32);
        k_splitBT2<<<gB, dim3(32, 8)>>>(W1, p_b2, HF2, 512, KPM);
        mma_gemm<<<2 * 4, 256, SMEM_MMA>>>(p_a2, p_b2, b1, p_m1,
                                           GG, 512, 512, KPM, 2, 4, 3);
    }

    // MLP tail (tiny)
    {
        dim3 grid(1, 2);
        sgemm<<<grid, 256>>>(p_m1, W2, b2, p_m2, GG, 128, 512, 1, 0);
    }
    {
        dim3 grid(1, 2);
        sgemm<<<grid, 256>>>(p_m2, W3, b3, out, GG, 64, 128, 1, 0);
    }
}

// round 11
// speedup vs baseline: 2.2017x; 1.4552x over previous
#include <cuda_runtime.h>
#include <cuda_fp16.h>
#include <cstdint>
#include <cstddef>

// ---------------- problem constants (fixed shapes) ----------------
#define NN    8000
#define EE    32000
#define ETOT  40000
#define GG    256
#define FF    680
#define HH    10
#define HFD   6800
#define HF2   13600

#define MP_G  8064
#define KP1   704
#define KP2   6848
#define KPM   13632
#define NPAD  6912

#define PCH   14

// ---------------- scratch ----------------
__device__ float g_xh [(size_t)NN * HFD];
__device__ float g_xw [(size_t)NN * HFD];
__device__ float g_h2 [(size_t)NN * HFD];
__device__ float g_als[NN * HH];
__device__ float g_ald[NN * HH];
__device__ float g_alpha[(size_t)ETOT * HH];
__device__ int   g_cnt[NN];
__device__ int   g_cur[NN];
__device__ int   g_start[NN + 1];
__device__ int   g_esrc[ETOT];
__device__ float g_dinv[NN];
__device__ int   g_pstart[GG];
__device__ int   g_pend[GG];
__device__ int   g_pcnt[GG];
__device__ float g_mlp1[GG * 512];
__device__ float g_mlp2[GG * 128];

// fp16 panels. A panel layout depends on use:
//  - GEMM1 (2-term): [MP_G rows, 2*KP1] hi|lo
//  - GEMM2 (1-term): [MP_G rows, KP2] hi only (written by gat_agg)
//  - MLP1  (2-term): [GG rows, 2*KPM] hi|lo (written by pool)
__device__ __half s_a2[(size_t)MP_G * (2 * KP2)];
__device__ __half s_b2[(size_t)NPAD * (2 * KP2)];   // B = hi-only [*, KP]

// ---------------- PTX helpers ----------------
__device__ __forceinline__ uint32_t smem_u32(const void* p) {
    uint32_t a;
    asm("{ .reg .u64 t; cvta.to.shared.u64 t, %1; cvt.u32.u64 %0, t; }" : "=r"(a) : "l"(p));
    return a;
}

__device__ __forceinline__ void cp16(uint32_t dst, const void* src) {
    asm volatile("cp.async.cg.shared.global [%0], [%1], 16;" :: "r"(dst), "l"(src));
}
#define CP_COMMIT() asm volatile("cp.async.commit_group;" ::: "memory")
__device__ __forceinline__ void cp_wait(int pend) {
    if (pend <= 0)      asm volatile("cp.async.wait_group 0;" ::: "memory");
    else                asm volatile("cp.async.wait_group 1;" ::: "memory");
}

__device__ __forceinline__ void ldsm4(uint32_t* r, uint32_t addr) {
    asm volatile("ldmatrix.sync.aligned.m8n8.x4.shared.b16 {%0,%1,%2,%3}, [%4];"
                 : "=r"(r[0]), "=r"(r[1]), "=r"(r[2]), "=r"(r[3]) : "r"(addr));
}

__device__ __forceinline__ void mma_f32acc(float* d, const uint32_t* a, uint32_t b0, uint32_t b1) {
    asm volatile("mma.sync.aligned.m16n8k16.row.col.f32.f16.f16.f32 "
                 "{%0,%1,%2,%3}, {%4,%5,%6,%7}, {%8,%9}, {%0,%1,%2,%3};"
                 : "+f"(d[0]), "+f"(d[1]), "+f"(d[2]), "+f"(d[3])
                 : "r"(a[0]), "r"(a[1]), "r"(a[2]), "r"(a[3]), "r"(b0), "r"(b1));
}

__device__ __forceinline__ uint32_t sm_tile_off(int row, int chunk) {
    return (uint32_t)(row * 64 + ((chunk ^ ((row >> 1) & 3)) << 4));
}

// ---------------- fp16 GEMM, TERMS = 1 (A_hi * B) or 2 ((A_hi+A_lo) * B) ----------------
#define BM 128
#define BN 128
#define BK 32
#define STG 3
#define SUB_BYTES 8192
#define SMEM_MMA_2 (STG * 3 * SUB_BYTES)   // 72KB
#define SMEM_MMA_1 (STG * 2 * SUB_BYTES)   // 48KB

template<int TERMS>
__global__ __launch_bounds__(256, 2) void mma_gemm(
    const __half* __restrict__ A2, const __half* __restrict__ B2,
    const float* __restrict__ bias, float* __restrict__ C,
    int M, int N, int ldc, int KP, int tiles_m, int tiles_n, int flags)
{
    constexpr int STAGE_BYTES = (TERMS + 1) * SUB_BYTES;
    extern __shared__ char smem[];
    uint32_t sb = smem_u32(smem);
    const int tid = threadIdx.x;
    const int wid = tid >> 5;
    const int lane = tid & 31;
    const int warp_m = wid & 3;
    const int warp_n = wid >> 2;

    int gm, gn;
    {
        const int GM = 8;
        int bid = blockIdx.x;
        int per = GM * tiles_n;
        int grp = bid / per;
        int fm  = grp * GM;
        int gsz = tiles_m - fm; if (gsz > GM) gsz = GM;
        int r = bid - grp * per;
        gm = fm + r % gsz;
        gn = r / gsz;
    }

    const int CH = KP / BK;
    const int KA = TERMS * KP;   // A panel row stride in elements

    const int lrow = tid >> 1;
    const int lc0  = (tid & 1) * 2;
    const __half* pA = A2 + (size_t)(gm * BM + lrow) * KA + lc0 * 8;
    const __half* pB = B2 + (size_t)(gn * BN + lrow) * KP + lc0 * 8;
    const uint32_t so0 = sm_tile_off(lrow, lc0);
    const uint32_t so1 = so0 ^ 16;

    const uint32_t aoff00 = sm_tile_off(warp_m * 32 + (lane & 15), (lane >> 4));
    const uint32_t boff00 = TERMS * SUB_BYTES + sm_tile_off(warp_n * 64 + (lane & 15), (lane >> 4));

    float acc[2][8][4];
#pragma unroll
    for (int mi = 0; mi < 2; mi++)
#pragma unroll
        for (int ni = 0; ni < 8; ni++)
#pragma unroll
            for (int j = 0; j < 4; j++) acc[mi][ni][j] = 0.f;

    // preload chunks 0,1
#pragma unroll
    for (int c = 0; c < 2 && c < CH; c++) {
        uint32_t stb = sb + c * STAGE_BYTES;
        int ko = c * BK;
        cp16(stb + so0, pA + ko);
        cp16(stb + so1, pA + ko + 8);
        if (TERMS == 2) {
            cp16(stb + SUB_BYTES + so0, pA + KP + ko);
            cp16(stb + SUB_BYTES + so1, pA + KP + ko + 8);
        }
        cp16(stb + TERMS * SUB_BYTES + so0, pB + ko);
        cp16(stb + TERMS * SUB_BYTES + so1, pB + ko + 8);
        CP_COMMIT();
    }

    int s = 0;
    int sload = 2;
    for (int c = 0; c < CH; c++) {
        cp_wait((CH - 1 - c) >= 1 ? 1 : 0);
        __syncthreads();

        if (c + 2 < CH) {
            uint32_t dtb = sb + sload * STAGE_BYTES;
            int ko = (c + 2) * BK;
            cp16(dtb + so0, pA + ko);
            cp16(dtb + so1, pA + ko + 8);
            if (TERMS == 2) {
                cp16(dtb + SUB_BYTES + so0, pA + KP + ko);
                cp16(dtb + SUB_BYTES + so1, pA + KP + ko + 8);
            }
            cp16(dtb + TERMS * SUB_BYTES + so0, pB + ko);
            cp16(dtb + TERMS * SUB_BYTES + so1, pB + ko + 8);
            CP_COMMIT();
        }

        uint32_t stb = sb + s * STAGE_BYTES;
#pragma unroll
        for (int ks = 0; ks < 2; ks++) {
            uint32_t ao = stb + (aoff00 ^ (ks * 32));
            uint32_t bo = stb + (boff00 ^ (ks * 32));
            uint32_t ahi[2][4], alo[2][4], bfr[4][4];
            ldsm4(ahi[0], ao);
            ldsm4(ahi[1], ao + 1024);
            if (TERMS == 2) {
                ldsm4(alo[0], ao + SUB_BYTES);
                ldsm4(alo[1], ao + SUB_BYTES + 1024);
            }
#pragma unroll
            for (int g = 0; g < 4; g++) ldsm4(bfr[g], bo + g * 1024);
            // pass1: hi * B
#pragma unroll
            for (int g = 0; g < 4; g++)
#pragma unroll
                for (int h = 0; h < 2; h++)
#pragma unroll
                    for (int mi = 0; mi < 2; mi++)
                        mma_f32acc(acc[mi][g * 2 + h], ahi[mi], bfr[g][h], bfr[g][h + 2]);
            // pass2: lo * B
            if (TERMS == 2) {
#pragma unroll
                for (int g = 0; g < 4; g++)
#pragma unroll
                    for (int h = 0; h < 2; h++)
#pragma unroll
                        for (int mi = 0; mi < 2; mi++)
                            mma_f32acc(acc[mi][g * 2 + h], alo[mi], bfr[g][h], bfr[g][h + 2]);
            }
        }
        s++; if (s == STG) s = 0;
        sload++; if (sload == STG) sload = 0;
    }

    // epilogue
    int erow0 = gm * BM + warp_m * 32 + (lane >> 2);
    int ecol0 = gn * BN + warp_n * 64 + (lane & 3) * 2;
#pragma unroll
    for (int mi = 0; mi < 2; mi++) {
#pragma unroll
        for (int ni = 0; ni < 8; ni++) {
            int r = erow0 + mi * 16;
            int cc = ecol0 + ni * 8;
#pragma unroll
            for (int half_i = 0; half_i < 2; half_i++) {
                int rr = r + half_i * 8;
                if (rr < M) {
                    float v0 = acc[mi][ni][half_i * 2 + 0];
                    float v1 = acc[mi][ni][half_i * 2 + 1];
                    if (cc < N) {
                        float o = v0;
                        if (flags & 1) o += bias[cc];
                        if (flags & 2) o = fmaxf(o, 0.f);
                        C[(size_t)rr * ldc + cc] = o;
                    }
                    if (cc + 1 < N) {
                        float o = v1;
                        if (flags & 1) o += bias[cc + 1];
                        if (flags & 2) o = fmaxf(o, 0.f);
                        C[(size_t)rr * ldc + cc + 1] = o;
                    }
                }
            }
        }
    }
}

// ---------------- conversion kernels ----------------
__device__ __forceinline__ uint32_t pack_h2(__half a, __half b) {
    return ((uint32_t)__half_as_ushort(b) << 16) | __half_as_ushort(a);
}

// A[M,K] fp32 -> [Mp, 2KP] fp16 hi|lo
__global__ void k_splitA2(const float* __restrict__ src, __half* __restrict__ dst,
                          int M, int K, int KP)
{
    int k = (blockIdx.x * 256 + threadIdx.x) * 4;
    int m = blockIdx.y;
    if (k >= KP) return;
    float4 v = make_float4(0.f, 0.f, 0.f, 0.f);
    if (m < M && k < K) v = *reinterpret_cast<const float4*>(&src[(size_t)m * K + k]);
    __half h0 = __float2half_rn(v.x), h1 = __float2half_rn(v.y);
    __half h2 = __float2half_rn(v.z), h3 = __float2half_rn(v.w);
    __half l0 = __float2half_rn(v.x - __half2float(h0));
    __half l1 = __float2half_rn(v.y - __half2float(h1));
    __half l2 = __float2half_rn(v.z - __half2float(h2));
    __half l3 = __float2half_rn(v.w - __half2float(h3));
    uint2 hp, lp;
    hp.x = pack_h2(h0, h1); hp.y = pack_h2(h2, h3);
    lp.x = pack_h2(l0, l1); lp.y = pack_h2(l2, l3);
    size_t base = (size_t)m * (2 * KP);
    *reinterpret_cast<uint2*>(&dst[base + k]) = hp;
    *reinterpret_cast<uint2*>(&dst[base + KP + k]) = lp;
}

// B[K,N] fp32 -> transposed [Np, KP] fp16 hi only
__global__ void k_splitBT2(const float* __restrict__ src, __half* __restrict__ dst,
                           int K, int N, int KP)
{
    __shared__ float t[64][33];
    int k0 = blockIdx.x * 64, n0 = blockIdx.y * 32;
    int tx = threadIdx.x, ty = threadIdx.y;   // 32 x 8
#pragma unroll
    for (int it = 0; it < 8; it++) {
        int k = k0 + ty + it * 8;
        int n = n0 + tx;
        t[ty + it * 8][tx] = (k < K && n < N) ? src[(size_t)k * N + n] : 0.f;
    }
    __syncthreads();
    int uid = ty * 32 + tx;
    int nl = uid >> 3;
    int kg = (uid & 7) * 8;
    size_t base = (size_t)(n0 + nl) * KP + k0;
#pragma unroll
    for (int q = 0; q < 4; q++) {
        int kk = kg + q * 2;
        float v0 = t[kk][nl], v1 = t[kk + 1][nl];
        *reinterpret_cast<uint32_t*>(&dst[base + kk]) =
            pack_h2(__float2half_rn(v0), __float2half_rn(v1));
    }
}

// ---------------- scalar SGEMM (tiny MLP tail layers) ----------------
__global__ __launch_bounds__(256) void sgemm(const float* __restrict__ A,
                                             const float* __restrict__ B,
                                             const float* __restrict__ bias,
                                             float* __restrict__ C,
                                             int M, int N, int K,
                                             int hasBias, int doRelu) {
    __shared__ float As[8][128];
    __shared__ float Bs[8][128];
    const int tid   = threadIdx.x;
    const int tileM = blockIdx.y * 128;
    const int tileN = blockIdx.x * 128;

    const int aRow = tid >> 1;
    const int aK4  = (tid & 1) * 4;
    const int bRow = tid >> 5;
    const int bCol = (tid & 31) * 4;
    const int ty   = tid >> 4;
    const int tx   = tid & 15;

    float acc[8][8];
#pragma unroll
    for (int i = 0; i < 8; i++)
#pragma unroll
        for (int j = 0; j < 8; j++) acc[i][j] = 0.f;

    for (int k0 = 0; k0 < K; k0 += 8) {
        float4 av = make_float4(0.f, 0.f, 0.f, 0.f);
        int gr = tileM + aRow;
        if (gr < M) av = *reinterpret_cast<const float4*>(&A[(size_t)gr * K + k0 + aK4]);
        As[aK4 + 0][aRow] = av.x;
        As[aK4 + 1][aRow] = av.y;
        As[aK4 + 2][aRow] = av.z;
        As[aK4 + 3][aRow] = av.w;

        float4 bv = make_float4(0.f, 0.f, 0.f, 0.f);
        int gc = tileN + bCol;
        const float* bp = &B[(size_t)(k0 + bRow) * N + gc];
        if (gc + 3 < N) {
            bv = *reinterpret_cast<const float4*>(bp);
        } else {
            if (gc + 0 < N) bv.x = bp[0];
            if (gc + 1 < N) bv.y = bp[1];
            if (gc + 2 < N) bv.z = bp[2];
            if (gc + 3 < N) bv.w = bp[3];
        }
        *reinterpret_cast<float4*>(&Bs[bRow][bCol]) = bv;

        __syncthreads();
#pragma unroll
        for (int kk = 0; kk < 8; kk++) {
            float a[8], b[8];
            *reinterpret_cast<float4*>(&a[0]) = *reinterpret_cast<float4*>(&As[kk][ty * 8]);
            *reinterpret_cast<float4*>(&a[4]) = *reinterpret_cast<float4*>(&As[kk][ty * 8 + 4]);
            *reinterpret_cast<float4*>(&b[0]) = *reinterpret_cast<float4*>(&Bs[kk][tx * 8]);
            *reinterpret_cast<float4*>(&b[4]) = *reinterpret_cast<float4*>(&Bs[kk][tx * 8 + 4]);
#pragma unroll
            for (int i = 0; i < 8; i++)
#pragma unroll
                for (int j = 0; j < 8; j++) acc[i][j] = fmaf(a[i], b[j], acc[i][j]);
        }
        __syncthreads();
    }

#pragma unroll
    for (int i = 0; i < 8; i++) {
        int row = tileM + ty * 8 + i;
        if (row >= M) continue;
#pragma unroll
        for (int j = 0; j < 8; j++) {
            int col = tileN + tx * 8 + j;
            if (col < N) {
                float v = acc[i][j];
                if (hasBias) v += bias[col];
                if (doRelu) v = fmaxf(v, 0.f);
                C[(size_t)row * N + col] = v;
            }
        }
    }
}

// ---------------- CSR build ----------------
__global__ void k_init() {
    int i = blockIdx.x * blockDim.x + threadIdx.x;
    if (i < NN) { g_cnt[i] = 0; g_cur[i] = 0; }
    if (i < GG) { g_pstart[i] = 0x7fffffff; g_pend[i] = -1; g_pcnt[i] = 0; }
}

__global__ void k_count(const int* __restrict__ ei) {
    int k = blockIdx.x * blockDim.x + threadIdx.x;
    if (k >= ETOT) return;
    int dst = (k < EE) ? ei[EE + k] : (k - EE);
    atomicAdd(&g_cnt[dst], 1);
}

__global__ __launch_bounds__(1024) void k_scan() {
    __shared__ int sd[1024];
    __shared__ int scarry;
    int tid = threadIdx.x;
    if (tid == 0) { scarry = 0; g_start[0] = 0; }
    __syncthreads();
    for (int base = 0; base < NN; base += 1024) {
        int v = (base + tid < NN) ? g_cnt[base + tid] : 0;
        sd[tid] = v;
        __syncthreads();
        for (int o = 1; o < 1024; o <<= 1) {
            int t = (tid >= o) ? sd[tid - o] : 0;
            __syncthreads();
            sd[tid] += t;
            __syncthreads();
        }
        int run = scarry;
        if (base + tid < NN) g_start[base + tid + 1] = run + sd[tid];
        __syncthreads();
        if (tid == 1023) scarry = run + sd[1023];
        __syncthreads();
    }
}

__global__ void k_scatter(const int* __restrict__ ei) {
    int k = blockIdx.x * blockDim.x + threadIdx.x;
    if (k >= ETOT) return;
    int src = (k < EE) ? ei[k]      : (k - EE);
    int dst = (k < EE) ? ei[EE + k] : (k - EE);
    int pos = g_start[dst] + atomicAdd(&g_cur[dst], 1);
    g_esrc[pos] = src;
}

__global__ void k_dinv() {
    int i = blockIdx.x * blockDim.x + threadIdx.x;
    if (i < NN) g_dinv[i] = rsqrtf((float)g_cnt[i]);
}

// ---------------- attention ----------------
__global__ void k_attn(const float* __restrict__ xh, const float* __restrict__ a_s,
                       const float* __restrict__ a_d) {
    int n = blockIdx.x;
    int w = threadIdx.x >> 5;
    int lane = threadIdx.x & 31;
    if (w >= HH) return;
    const float* row = xh + (size_t)n * HFD + w * FF;
    const float* as  = a_s + w * FF;
    const float* ad  = a_d + w * FF;
    float s1 = 0.f, s2 = 0.f;
    for (int f = lane; f < FF; f += 32) {
        float v = row[f];
        s1 = fmaf(v, as[f], s1);
        s2 = fmaf(v, ad[f], s2);
    }
#pragma unroll
    for (int o = 16; o; o >>= 1) {
        s1 += __shfl_down_sync(0xffffffffu, s1, o);
        s2 += __shfl_down_sync(0xffffffffu, s2, o);
    }
    if (lane == 0) { g_als[n * HH + w] = s1; g_ald[n * HH + w] = s2; }
}

__global__ void k_softmax() {
    int node = blockIdx.x * blockDim.y + threadIdx.y;
    if (node >= NN) return;
    int lane = threadIdx.x;
    bool act = lane < HH;
    int s = g_start[node], e = g_start[node + 1];
    float ald_v = act ? g_ald[node * HH + lane] : 0.f;
    float mx = -3.0e38f;
    for (int p = s; p < e; p++) {
        int src = g_esrc[p];
        if (act) {
            float v = g_als[src * HH + lane] + ald_v;
            v = fmaxf(v, 0.2f * v);
            mx = fmaxf(mx, v);
        }
    }
    float z = 0.f;
    for (int p = s; p < e; p++) {
        int src = g_esrc[p];
        if (act) {
            float v = g_als[src * HH + lane] + ald_v;
            v = fmaxf(v, 0.2f * v);
            float ex = expf(v - mx);
            g_alpha[(size_t)p * HH + lane] = ex;
            z += ex;
        }
    }
    float inv = 1.f / (z + 1e-16f);
    for (int p = s; p < e; p++)
        if (act) g_alpha[(size_t)p * HH + lane] *= inv;
}

// ---------------- GAT aggregation -> hi-only fp16 A panel [MP_G, KP2] ----------------
__global__ __launch_bounds__(256) void k_gat_agg_split(const float* __restrict__ bias) {
    int n = blockIdx.x, tid = threadIdx.x;
    __half* arow = s_a2 + (size_t)n * KP2;
    if (n >= NN) {
        for (int k = tid; k < KP2 / 2; k += 256)
            reinterpret_cast<uint32_t*>(arow)[k] = 0;
        return;
    }
    int s = g_start[n], e = g_start[n + 1];
    float2 acc[PCH];
    int hidx[PCH];
#pragma unroll
    for (int i = 0; i < PCH; i++) {
        int f = 2 * tid + 512 * i;
        hidx[i] = (f < HFD) ? (f / FF) : 0;
        acc[i].x = (f < HFD) ? bias[f] : 0.f;
        acc[i].y = (f + 1 < HFD) ? bias[f + 1] : 0.f;
    }
    for (int p = s; p < e; p++) {
        int src = g_esrc[p];
        const float2* xr = reinterpret_cast<const float2*>(g_xh + (size_t)src * HFD);
        const float* al = g_alpha + (size_t)p * HH;
#pragma unroll
        for (int i = 0; i < PCH; i++) {
            int f = 2 * tid + 512 * i;
            if (f < HFD) {
                float2 v = xr[f >> 1];
                float a = al[hidx[i]];
                acc[i].x = fmaf(a, v.x, acc[i].x);
                acc[i].y = fmaf(a, v.y, acc[i].y);
            }
        }
    }
#pragma unroll
    for (int i = 0; i < PCH; i++) {
        int f = 2 * tid + 512 * i;
        if (f < KP2) {
            float vx = (f < HFD) ? fmaxf(acc[i].x, 0.f) : 0.f;
            float vy = (f + 1 < HFD) ? fmaxf(acc[i].y, 0.f) : 0.f;
            *reinterpret_cast<uint32_t*>(&arow[f]) =
                pack_h2(__float2half_rn(vx), __float2half_rn(vy));
        }
    }
}

// ---------------- GCN aggregation ----------------
#define FCH 27
__global__ __launch_bounds__(256) void k_gcn_agg(const float* __restrict__ bias) {
    int n = blockIdx.x, tid = threadIdx.x;
    int s = g_start[n], e = g_start[n + 1];
    float dv = g_dinv[n];
    float acc[FCH];
#pragma unroll
    for (int i = 0; i < FCH; i++) {
        int f = tid + i * 256;
        acc[i] = (f < HFD) ? bias[f] : 0.f;
    }
    for (int p = s; p < e; p++) {
        int src = g_esrc[p];
        float coef = g_dinv[src] * dv;
        const float* xr = g_xw + (size_t)src * HFD;
#pragma unroll
        for (int i = 0; i < FCH; i++) {
            int f = tid + i * 256;
            if (f < HFD) acc[i] = fmaf(coef, xr[f], acc[i]);
        }
    }
    float* o = g_h2 + (size_t)n * HFD;
#pragma unroll
    for (int i = 0; i < FCH; i++) {
        int f = tid + i * 256;
        if (f < HFD) o[f] = fmaxf(acc[i], 0.f);
    }
}

// ---------------- pooling fused with MLP1 A-panel split ----------------
__global__ void k_ranges(const int* __restrict__ batch) {
    int i = blockIdx.x * blockDim.x + threadIdx.x;
    if (i >= NN) return;
    int b = batch[i];
    if (b >= 0 && b < GG) {
        atomicMin(&g_pstart[b], i);
        atomicMax(&g_pend[b], i);
        atomicAdd(&g_pcnt[b], 1);
    }
}

__device__ __forceinline__ void h_split_store(__half* hi, __half* lo, float v) {
    __half h = __float2half_rn(v);
    *hi = h;
    *lo = __float2half_rn(v - __half2float(h));
}

__global__ __launch_bounds__(256) void k_pool_split() {
    int g = blockIdx.y;
    int f = blockIdx.x * blockDim.x + threadIdx.x;
    if (f >= HFD) return;
    int s = g_pstart[g], e = g_pend[g];
    float mx = -3.0e38f, sm = 0.f;
    for (int n = s; n <= e; n++) {
        float v = g_h2[(size_t)n * HFD + f];
        mx = fmaxf(mx, v);
        sm += v;
    }
    float gap = sm / (float)g_pcnt[g];
    __half* row = s_a2 + (size_t)g * (2 * KPM);
    h_split_store(&row[f],       &row[KPM + f],       mx);
    h_split_store(&row[HFD + f], &row[KPM + HFD + f], gap);
}

__global__ void k_pool_pad() {
    int g = blockIdx.x;
    int t = threadIdx.x;
    __half* row = s_a2 + (size_t)g * (2 * KPM);
    row[HF2 + t] = __float2half_rn(0.f);
    row[KPM + HF2 + t] = __float2half_rn(0.f);
}

// ---------------- launch ----------------
extern "C" void kernel_launch(void* const* d_in, const int* in_sizes, int n_in,
                              void* d_out, int out_size) {
    const float* x     = (const float*)d_in[0];
    const int*   ei    = (const int*)  d_in[1];
    const int*   batch = (const int*)  d_in[2];
    const float* W_gat = (const float*)d_in[3];
    const float* a_src = (const float*)d_in[4];
    const float* a_dst = (const float*)d_in[5];
    const float* b_gat = (const float*)d_in[6];
    const float* W_gcn = (const float*)d_in[7];
    const float* b_gcn = (const float*)d_in[8];
    const float* W1    = (const float*)d_in[9];
    const float* b1    = (const float*)d_in[10];
    const float* W2    = (const float*)d_in[11];
    const float* b2    = (const float*)d_in[12];
    const float* W3    = (const float*)d_in[13];
    const float* b3    = (const float*)d_in[14];
    float* out = (float*)d_out;

    float *p_xh, *p_xw, *p_m1, *p_m2;
    __half *p_a2, *p_b2;
    cudaGetSymbolAddress((void**)&p_xh,   g_xh);
    cudaGetSymbolAddress((void**)&p_xw,   g_xw);
    cudaGetSymbolAddress((void**)&p_m1,   g_mlp1);
    cudaGetSymbolAddress((void**)&p_m2,   g_mlp2);
    cudaGetSymbolAddress((void**)&p_a2,   s_a2);
    cudaGetSymbolAddress((void**)&p_b2,   s_b2);

    cudaFuncSetAttribute(mma_gemm<2>, cudaFuncAttributeMaxDynamicSharedMemorySize, SMEM_MMA_2);
    cudaFuncSetAttribute(mma_gemm<1>, cudaFuncAttributeMaxDynamicSharedMemorySize, SMEM_MMA_1);

    const int TM = MP_G / 128;   // 63
    const int TN = NPAD / 128;   // 54

    // ---- GEMM1 (2-term): xh = x @ W_gat; mma at launch index 3 (ncu slot) ----
    {
        dim3 gA((KP1 / 4 + 255) / 256, MP_G);
        k_splitA2<<<gA, 256>>>(x, p_a2, NN, FF, KP1);                 // 0
        dim3 gB(KP1 / 64, NPAD / 32);
        k_splitBT2<<<gB, dim3(32, 8)>>>(W_gat, p_b2, FF, HFD, KP1);   // 1
    }
    k_init<<<(NN + 255) / 256, 256>>>();                               // 2
    mma_gemm<2><<<TM * TN, 256, SMEM_MMA_2>>>(p_a2, p_b2, nullptr, p_xh,  // 3
                                              NN, HFD, HFD, KP1, TM, TN, 0);

    // CSR build + degrees
    k_count<<<(ETOT + 255) / 256, 256>>>(ei);
    k_scan<<<1, 1024>>>();
    k_scatter<<<(ETOT + 255) / 256, 256>>>(ei);
    k_dinv<<<(NN + 255) / 256, 256>>>();

    k_attn<<<NN, 320>>>(p_xh, a_src, a_dst);
    k_softmax<<<(NN + 7) / 8, dim3(32, 8)>>>();
    k_gat_agg_split<<<MP_G, 256>>>(b_gat);   // writes hi-only A panel [MP_G, KP2]

    // ---- GEMM2 (1-term, pure fp16 A): xw = h @ W_gcn ----
    {
        dim3 gB(KP2 / 64, NPAD / 32);
        k_splitBT2<<<gB, dim3(32, 8)>>>(W_gcn, p_b2, HFD, HFD, KP2);
        mma_gemm<1><<<TM * TN, 256, SMEM_MMA_1>>>(p_a2, p_b2, nullptr, p_xw,
                                                  NN, HFD, HFD, KP2, TM, TN, 0);
    }

    k_gcn_agg<<<NN, 256>>>(b_gcn);

    // pooling (writes MLP1 A-panel hi/lo)
    k_ranges<<<(NN + 255) / 256, 256>>>(batch);
    {
        dim3 grid((HFD + 255) / 256, GG);
        k_pool_split<<<grid, 256>>>();
        k_pool_pad<<<GG, 32>>>();
    }

    // ---- MLP1 (2-term): relu(pool @ W1 + b1) ----
    {
        dim3 gB(KPM / 64, 512 / 32);
        k_splitBT2<<<gB, dim3(32, 8)>>>(W1, p_b2, HF2, 512, KPM);
        mma_gemm<2><<<2 * 4, 256, SMEM_MMA_2>>>(p_a2, p_b2, b1, p_m1,
                                                GG, 512, 512, KPM, 2, 4, 3);
    }

    // MLP tail (tiny)
    {
        dim3 grid(1, 2);
        sgemm<<<grid, 256>>>(p_m1, W2, b2, p_m2, GG, 128, 512, 1, 0);
    }
    {
        dim3 grid(1, 2);
        sgemm<<<grid, 256>>>(p_m2, W3, b3, out, GG, 64, 128, 1, 0);
    }
}

// round 12
// speedup vs baseline: 2.2940x; 1.0419x over previous
#include <cuda_runtime.h>
#include <cuda_fp16.h>
#include <cstdint>
#include <cstddef>

// ---------------- problem constants (fixed shapes) ----------------
#define NN    8000
#define EE    32000
#define ETOT  40000
#define GG    256
#define FF    680
#define HH    10
#define HFD   6800
#define HF2   13600

#define MP_G  8064
#define KP1   704
#define KP2   6848
#define KPM   13632
#define NPAD  6912

#define PCH   14

// ---------------- scratch ----------------
__device__ float  g_xh  [(size_t)NN * HFD];   // fp32 xh (attention)
__device__ __half g_xh16[(size_t)NN * HFD];   // fp16 xh (gat gather)
__device__ __half g_xw16[(size_t)NN * HFD];   // fp16 xw (gcn gather)
__device__ float  g_h2  [(size_t)NN * HFD];
__device__ float g_als[NN * HH];
__device__ float g_ald[NN * HH];
__device__ float g_alpha[(size_t)ETOT * HH];
__device__ int   g_cnt[NN];
__device__ int   g_cur[NN];
__device__ int   g_start[NN + 1];
__device__ int   g_esrc[ETOT];
__device__ float g_dinv[NN];
__device__ int   g_pstart[GG];
__device__ int   g_pend[GG];
__device__ int   g_pcnt[GG];
__device__ float g_mlp1[GG * 512];
__device__ float g_mlp2[GG * 128];

// fp16 panels. A panel layout depends on use:
//  - GEMM1 (2-term): [MP_G rows, 2*KP1] hi|lo
//  - GEMM2 (1-term): [MP_G rows, KP2] hi only (written by gat_agg)
//  - MLP1  (2-term): [GG rows, 2*KPM] hi|lo (written by pool)
__device__ __half s_a2[(size_t)MP_G * (2 * KP2)];
__device__ __half s_b2[(size_t)NPAD * (2 * KP2)];   // B = hi-only [*, KP]

// ---------------- PTX helpers ----------------
__device__ __forceinline__ uint32_t smem_u32(const void* p) {
    uint32_t a;
    asm("{ .reg .u64 t; cvta.to.shared.u64 t, %1; cvt.u32.u64 %0, t; }" : "=r"(a) : "l"(p));
    return a;
}

__device__ __forceinline__ void cp16(uint32_t dst, const void* src) {
    asm volatile("cp.async.cg.shared.global [%0], [%1], 16;" :: "r"(dst), "l"(src));
}
#define CP_COMMIT() asm volatile("cp.async.commit_group;" ::: "memory")
__device__ __forceinline__ void cp_wait(int pend) {
    if (pend <= 0)      asm volatile("cp.async.wait_group 0;" ::: "memory");
    else                asm volatile("cp.async.wait_group 1;" ::: "memory");
}

__device__ __forceinline__ void ldsm4(uint32_t* r, uint32_t addr) {
    asm volatile("ldmatrix.sync.aligned.m8n8.x4.shared.b16 {%0,%1,%2,%3}, [%4];"
                 : "=r"(r[0]), "=r"(r[1]), "=r"(r[2]), "=r"(r[3]) : "r"(addr));
}

__device__ __forceinline__ void mma_f32acc(float* d, const uint32_t* a, uint32_t b0, uint32_t b1) {
    asm volatile("mma.sync.aligned.m16n8k16.row.col.f32.f16.f16.f32 "
                 "{%0,%1,%2,%3}, {%4,%5,%6,%7}, {%8,%9}, {%0,%1,%2,%3};"
                 : "+f"(d[0]), "+f"(d[1]), "+f"(d[2]), "+f"(d[3])
                 : "r"(a[0]), "r"(a[1]), "r"(a[2]), "r"(a[3]), "r"(b0), "r"(b1));
}

__device__ __forceinline__ uint32_t sm_tile_off(int row, int chunk) {
    return (uint32_t)(row * 64 + ((chunk ^ ((row >> 1) & 3)) << 4));
}

// ---------------- fp16 GEMM, TERMS = 1 (A_hi * B) or 2 ((A_hi+A_lo) * B) ----------------
// flags: 1=bias, 2=relu, 4=store fp16 copy to C16, 8=skip fp32 store
#define BM 128
#define BN 128
#define BK 32
#define STG 3
#define SUB_BYTES 8192
#define SMEM_MMA_2 (STG * 3 * SUB_BYTES)   // 72KB
#define SMEM_MMA_1 (STG * 2 * SUB_BYTES)   // 48KB

template<int TERMS>
__global__ __launch_bounds__(256, 2) void mma_gemm(
    const __half* __restrict__ A2, const __half* __restrict__ B2,
    const float* __restrict__ bias, float* __restrict__ C, __half* __restrict__ C16,
    int M, int N, int ldc, int KP, int tiles_m, int tiles_n, int flags)
{
    constexpr int STAGE_BYTES = (TERMS + 1) * SUB_BYTES;
    extern __shared__ char smem[];
    uint32_t sb = smem_u32(smem);
    const int tid = threadIdx.x;
    const int wid = tid >> 5;
    const int lane = tid & 31;
    const int warp_m = wid & 3;
    const int warp_n = wid >> 2;

    int gm, gn;
    {
        const int GM = 8;
        int bid = blockIdx.x;
        int per = GM * tiles_n;
        int grp = bid / per;
        int fm  = grp * GM;
        int gsz = tiles_m - fm; if (gsz > GM) gsz = GM;
        int r = bid - grp * per;
        gm = fm + r % gsz;
        gn = r / gsz;
    }

    const int CH = KP / BK;
    const int KA = TERMS * KP;

    const int lrow = tid >> 1;
    const int lc0  = (tid & 1) * 2;
    const __half* pA = A2 + (size_t)(gm * BM + lrow) * KA + lc0 * 8;
    const __half* pB = B2 + (size_t)(gn * BN + lrow) * KP + lc0 * 8;
    const uint32_t so0 = sm_tile_off(lrow, lc0);
    const uint32_t so1 = so0 ^ 16;

    const uint32_t aoff00 = sm_tile_off(warp_m * 32 + (lane & 15), (lane >> 4));
    const uint32_t boff00 = TERMS * SUB_BYTES + sm_tile_off(warp_n * 64 + (lane & 15), (lane >> 4));

    float acc[2][8][4];
#pragma unroll
    for (int mi = 0; mi < 2; mi++)
#pragma unroll
        for (int ni = 0; ni < 8; ni++)
#pragma unroll
            for (int j = 0; j < 4; j++) acc[mi][ni][j] = 0.f;

    // preload chunks 0,1
#pragma unroll
    for (int c = 0; c < 2 && c < CH; c++) {
        uint32_t stb = sb + c * STAGE_BYTES;
        int ko = c * BK;
        cp16(stb + so0, pA + ko);
        cp16(stb + so1, pA + ko + 8);
        if (TERMS == 2) {
            cp16(stb + SUB_BYTES + so0, pA + KP + ko);
            cp16(stb + SUB_BYTES + so1, pA + KP + ko + 8);
        }
        cp16(stb + TERMS * SUB_BYTES + so0, pB + ko);
        cp16(stb + TERMS * SUB_BYTES + so1, pB + ko + 8);
        CP_COMMIT();
    }

    int s = 0;
    int sload = 2;
    for (int c = 0; c < CH; c++) {
        cp_wait((CH - 1 - c) >= 1 ? 1 : 0);
        __syncthreads();

        if (c + 2 < CH) {
            uint32_t dtb = sb + sload * STAGE_BYTES;
            int ko = (c + 2) * BK;
            cp16(dtb + so0, pA + ko);
            cp16(dtb + so1, pA + ko + 8);
            if (TERMS == 2) {
                cp16(dtb + SUB_BYTES + so0, pA + KP + ko);
                cp16(dtb + SUB_BYTES + so1, pA + KP + ko + 8);
            }
            cp16(dtb + TERMS * SUB_BYTES + so0, pB + ko);
            cp16(dtb + TERMS * SUB_BYTES + so1, pB + ko + 8);
            CP_COMMIT();
        }

        uint32_t stb = sb + s * STAGE_BYTES;
#pragma unroll
        for (int ks = 0; ks < 2; ks++) {
            uint32_t ao = stb + (aoff00 ^ (ks * 32));
            uint32_t bo = stb + (boff00 ^ (ks * 32));
            uint32_t ahi[2][4], alo[2][4], bfr[4][4];
            ldsm4(ahi[0], ao);
            ldsm4(ahi[1], ao + 1024);
            if (TERMS == 2) {
                ldsm4(alo[0], ao + SUB_BYTES);
                ldsm4(alo[1], ao + SUB_BYTES + 1024);
            }
#pragma unroll
            for (int g = 0; g < 4; g++) ldsm4(bfr[g], bo + g * 1024);
#pragma unroll
            for (int g = 0; g < 4; g++)
#pragma unroll
                for (int h = 0; h < 2; h++)
#pragma unroll
                    for (int mi = 0; mi < 2; mi++)
                        mma_f32acc(acc[mi][g * 2 + h], ahi[mi], bfr[g][h], bfr[g][h + 2]);
            if (TERMS == 2) {
#pragma unroll
                for (int g = 0; g < 4; g++)
#pragma unroll
                    for (int h = 0; h < 2; h++)
#pragma unroll
                        for (int mi = 0; mi < 2; mi++)
                            mma_f32acc(acc[mi][g * 2 + h], alo[mi], bfr[g][h], bfr[g][h + 2]);
            }
        }
        s++; if (s == STG) s = 0;
        sload++; if (sload == STG) sload = 0;
    }

    // epilogue (N is even, cc is even -> cc<N implies cc+1<N)
    int erow0 = gm * BM + warp_m * 32 + (lane >> 2);
    int ecol0 = gn * BN + warp_n * 64 + (lane & 3) * 2;
#pragma unroll
    for (int mi = 0; mi < 2; mi++) {
#pragma unroll
        for (int ni = 0; ni < 8; ni++) {
            int r = erow0 + mi * 16;
            int cc = ecol0 + ni * 8;
#pragma unroll
            for (int half_i = 0; half_i < 2; half_i++) {
                int rr = r + half_i * 8;
                if (rr < M && cc < N) {
                    float o0 = acc[mi][ni][half_i * 2 + 0];
                    float o1 = acc[mi][ni][half_i * 2 + 1];
                    if (flags & 1) { o0 += bias[cc]; o1 += bias[cc + 1]; }
                    if (flags & 2) { o0 = fmaxf(o0, 0.f); o1 = fmaxf(o1, 0.f); }
                    size_t idx = (size_t)rr * ldc + cc;
                    if (!(flags & 8)) { C[idx] = o0; C[idx + 1] = o1; }
                    if (flags & 4)
                        *reinterpret_cast<__half2*>(&C16[idx]) = __floats2half2_rn(o0, o1);
                }
            }
        }
    }
}

// ---------------- conversion kernels ----------------
__device__ __forceinline__ uint32_t pack_h2(__half a, __half b) {
    return ((uint32_t)__half_as_ushort(b) << 16) | __half_as_ushort(a);
}

// A[M,K] fp32 -> [Mp, 2KP] fp16 hi|lo
__global__ void k_splitA2(const float* __restrict__ src, __half* __restrict__ dst,
                          int M, int K, int KP)
{
    int k = (blockIdx.x * 256 + threadIdx.x) * 4;
    int m = blockIdx.y;
    if (k >= KP) return;
    float4 v = make_float4(0.f, 0.f, 0.f, 0.f);
    if (m < M && k < K) v = *reinterpret_cast<const float4*>(&src[(size_t)m * K + k]);
    __half h0 = __float2half_rn(v.x), h1 = __float2half_rn(v.y);
    __half h2 = __float2half_rn(v.z), h3 = __float2half_rn(v.w);
    __half l0 = __float2half_rn(v.x - __half2float(h0));
    __half l1 = __float2half_rn(v.y - __half2float(h1));
    __half l2 = __float2half_rn(v.z - __half2float(h2));
    __half l3 = __float2half_rn(v.w - __half2float(h3));
    uint2 hp, lp;
    hp.x = pack_h2(h0, h1); hp.y = pack_h2(h2, h3);
    lp.x = pack_h2(l0, l1); lp.y = pack_h2(l2, l3);
    size_t base = (size_t)m * (2 * KP);
    *reinterpret_cast<uint2*>(&dst[base + k]) = hp;
    *reinterpret_cast<uint2*>(&dst[base + KP + k]) = lp;
}

// B[K,N] fp32 -> transposed [Np, KP] fp16 hi only
__global__ void k_splitBT2(const float* __restrict__ src, __half* __restrict__ dst,
                           int K, int N, int KP)
{
    __shared__ float t[64][33];
    int k0 = blockIdx.x * 64, n0 = blockIdx.y * 32;
    int tx = threadIdx.x, ty = threadIdx.y;   // 32 x 8
#pragma unroll
    for (int it = 0; it < 8; it++) {
        int k = k0 + ty + it * 8;
        int n = n0 + tx;
        t[ty + it * 8][tx] = (k < K && n < N) ? src[(size_t)k * N + n] : 0.f;
    }
    __syncthreads();
    int uid = ty * 32 + tx;
    int nl = uid >> 3;
    int kg = (uid & 7) * 8;
    size_t base = (size_t)(n0 + nl) * KP + k0;
#pragma unroll
    for (int q = 0; q < 4; q++) {
        int kk = kg + q * 2;
        float v0 = t[kk][nl], v1 = t[kk + 1][nl];
        *reinterpret_cast<uint32_t*>(&dst[base + kk]) =
            pack_h2(__float2half_rn(v0), __float2half_rn(v1));
    }
}

// ---------------- scalar SGEMM (tiny MLP tail layers) ----------------
__global__ __launch_bounds__(256) void sgemm(const float* __restrict__ A,
                                             const float* __restrict__ B,
                                             const float* __restrict__ bias,
                                             float* __restrict__ C,
                                             int M, int N, int K,
                                             int hasBias, int doRelu) {
    __shared__ float As[8][128];
    __shared__ float Bs[8][128];
    const int tid   = threadIdx.x;
    const int tileM = blockIdx.y * 128;
    const int tileN = blockIdx.x * 128;

    const int aRow = tid >> 1;
    const int aK4  = (tid & 1) * 4;
    const int bRow = tid >> 5;
    const int bCol = (tid & 31) * 4;
    const int ty   = tid >> 4;
    const int tx   = tid & 15;

    float acc[8][8];
#pragma unroll
    for (int i = 0; i < 8; i++)
#pragma unroll
        for (int j = 0; j < 8; j++) acc[i][j] = 0.f;

    for (int k0 = 0; k0 < K; k0 += 8) {
        float4 av = make_float4(0.f, 0.f, 0.f, 0.f);
        int gr = tileM + aRow;
        if (gr < M) av = *reinterpret_cast<const float4*>(&A[(size_t)gr * K + k0 + aK4]);
        As[aK4 + 0][aRow] = av.x;
        As[aK4 + 1][aRow] = av.y;
        As[aK4 + 2][aRow] = av.z;
        As[aK4 + 3][aRow] = av.w;

        float4 bv = make_float4(0.f, 0.f, 0.f, 0.f);
        int gc = tileN + bCol;
        const float* bp = &B[(size_t)(k0 + bRow) * N + gc];
        if (gc + 3 < N) {
            bv = *reinterpret_cast<const float4*>(bp);
        } else {
            if (gc + 0 < N) bv.x = bp[0];
            if (gc + 1 < N) bv.y = bp[1];
            if (gc + 2 < N) bv.z = bp[2];
            if (gc + 3 < N) bv.w = bp[3];
        }
        *reinterpret_cast<float4*>(&Bs[bRow][bCol]) = bv;

        __syncthreads();
#pragma unroll
        for (int kk = 0; kk < 8; kk++) {
            float a[8], b[8];
            *reinterpret_cast<float4*>(&a[0]) = *reinterpret_cast<float4*>(&As[kk][ty * 8]);
            *reinterpret_cast<float4*>(&a[4]) = *reinterpret_cast<float4*>(&As[kk][ty * 8 + 4]);
            *reinterpret_cast<float4*>(&b[0]) = *reinterpret_cast<float4*>(&Bs[kk][tx * 8]);
            *reinterpret_cast<float4*>(&b[4]) = *reinterpret_cast<float4*>(&Bs[kk][tx * 8 + 4]);
#pragma unroll
            for (int i = 0; i < 8; i++)
#pragma unroll
                for (int j = 0; j < 8; j++) acc[i][j] = fmaf(a[i], b[j], acc[i][j]);
        }
        __syncthreads();
    }

#pragma unroll
    for (int i = 0; i < 8; i++) {
        int row = tileM + ty * 8 + i;
        if (row >= M) continue;
#pragma unroll
        for (int j = 0; j < 8; j++) {
            int col = tileN + tx * 8 + j;
            if (col < N) {
                float v = acc[i][j];
                if (hasBias) v += bias[col];
                if (doRelu) v = fmaxf(v, 0.f);
                C[(size_t)row * N + col] = v;
            }
        }
    }
}

// ---------------- CSR build ----------------
__global__ void k_init() {
    int i = blockIdx.x * blockDim.x + threadIdx.x;
    if (i < NN) { g_cnt[i] = 0; g_cur[i] = 0; }
    if (i < GG) { g_pstart[i] = 0x7fffffff; g_pend[i] = -1; g_pcnt[i] = 0; }
}

__global__ void k_count(const int* __restrict__ ei) {
    int k = blockIdx.x * blockDim.x + threadIdx.x;
    if (k >= ETOT) return;
    int dst = (k < EE) ? ei[EE + k] : (k - EE);
    atomicAdd(&g_cnt[dst], 1);
}

__global__ __launch_bounds__(1024) void k_scan() {
    __shared__ int sd[1024];
    __shared__ int scarry;
    int tid = threadIdx.x;
    if (tid == 0) { scarry = 0; g_start[0] = 0; }
    __syncthreads();
    for (int base = 0; base < NN; base += 1024) {
        int v = (base + tid < NN) ? g_cnt[base + tid] : 0;
        sd[tid] = v;
        __syncthreads();
        for (int o = 1; o < 1024; o <<= 1) {
            int t = (tid >= o) ? sd[tid - o] : 0;
            __syncthreads();
            sd[tid] += t;
            __syncthreads();
        }
        int run = scarry;
        if (base + tid < NN) g_start[base + tid + 1] = run + sd[tid];
        __syncthreads();
        if (tid == 1023) scarry = run + sd[1023];
        __syncthreads();
    }
}

__global__ void k_scatter(const int* __restrict__ ei) {
    int k = blockIdx.x * blockDim.x + threadIdx.x;
    if (k >= ETOT) return;
    int src = (k < EE) ? ei[k]      : (k - EE);
    int dst = (k < EE) ? ei[EE + k] : (k - EE);
    int pos = g_start[dst] + atomicAdd(&g_cur[dst], 1);
    g_esrc[pos] = src;
}

__global__ void k_dinv() {
    int i = blockIdx.x * blockDim.x + threadIdx.x;
    if (i < NN) g_dinv[i] = rsqrtf((float)g_cnt[i]);
}

// ---------------- attention ----------------
__global__ void k_attn(const float* __restrict__ xh, const float* __restrict__ a_s,
                       const float* __restrict__ a_d) {
    int n = blockIdx.x;
    int w = threadIdx.x >> 5;
    int lane = threadIdx.x & 31;
    if (w >= HH) return;
    const float* row = xh + (size_t)n * HFD + w * FF;
    const float* as  = a_s + w * FF;
    const float* ad  = a_d + w * FF;
    float s1 = 0.f, s2 = 0.f;
    for (int f = lane; f < FF; f += 32) {
        float v = row[f];
        s1 = fmaf(v, as[f], s1);
        s2 = fmaf(v, ad[f], s2);
    }
#pragma unroll
    for (int o = 16; o; o >>= 1) {
        s1 += __shfl_down_sync(0xffffffffu, s1, o);
        s2 += __shfl_down_sync(0xffffffffu, s2, o);
    }
    if (lane == 0) { g_als[n * HH + w] = s1; g_ald[n * HH + w] = s2; }
}

__global__ void k_softmax() {
    int node = blockIdx.x * blockDim.y + threadIdx.y;
    if (node >= NN) return;
    int lane = threadIdx.x;
    bool act = lane < HH;
    int s = g_start[node], e = g_start[node + 1];
    float ald_v = act ? g_ald[node * HH + lane] : 0.f;
    float mx = -3.0e38f;
    for (int p = s; p < e; p++) {
        int src = g_esrc[p];
        if (act) {
            float v = g_als[src * HH + lane] + ald_v;
            v = fmaxf(v, 0.2f * v);
            mx = fmaxf(mx, v);
        }
    }
    float z = 0.f;
    for (int p = s; p < e; p++) {
        int src = g_esrc[p];
        if (act) {
            float v = g_als[src * HH + lane] + ald_v;
            v = fmaxf(v, 0.2f * v);
            float ex = expf(v - mx);
            g_alpha[(size_t)p * HH + lane] = ex;
            z += ex;
        }
    }
    float inv = 1.f / (z + 1e-16f);
    for (int p = s; p < e; p++)
        if (act) g_alpha[(size_t)p * HH + lane] *= inv;
}

// ---------------- GAT aggregation (fp16 gather) -> hi-only fp16 A panel [MP_G, KP2] ----------------
__global__ __launch_bounds__(256) void k_gat_agg_split(const float* __restrict__ bias) {
    int n = blockIdx.x, tid = threadIdx.x;
    __half* arow = s_a2 + (size_t)n * KP2;
    if (n >= NN) {
        for (int k = tid; k < KP2 / 2; k += 256)
            reinterpret_cast<uint32_t*>(arow)[k] = 0;
        return;
    }
    int s = g_start[n], e = g_start[n + 1];
    float2 acc[PCH];
    int hidx[PCH];
#pragma unroll
    for (int i = 0; i < PCH; i++) {
        int f = 2 * tid + 512 * i;
        hidx[i] = (f < HFD) ? (f / FF) : 0;
        acc[i].x = (f < HFD) ? bias[f] : 0.f;
        acc[i].y = (f + 1 < HFD) ? bias[f + 1] : 0.f;
    }
    for (int p = s; p < e; p++) {
        int src = g_esrc[p];
        const __half2* xr = reinterpret_cast<const __half2*>(g_xh16 + (size_t)src * HFD);
        const float* al = g_alpha + (size_t)p * HH;
#pragma unroll
        for (int i = 0; i < PCH; i++) {
            int f = 2 * tid + 512 * i;
            if (f < HFD) {
                float2 v = __half22float2(xr[f >> 1]);
                float a = al[hidx[i]];
                acc[i].x = fmaf(a, v.x, acc[i].x);
                acc[i].y = fmaf(a, v.y, acc[i].y);
            }
        }
    }
#pragma unroll
    for (int i = 0; i < PCH; i++) {
        int f = 2 * tid + 512 * i;
        if (f < KP2) {
            float vx = (f < HFD) ? fmaxf(acc[i].x, 0.f) : 0.f;
            float vy = (f + 1 < HFD) ? fmaxf(acc[i].y, 0.f) : 0.f;
            *reinterpret_cast<uint32_t*>(&arow[f]) =
                pack_h2(__float2half_rn(vx), __float2half_rn(vy));
        }
    }
}

// ---------------- GCN aggregation (fp16 gather, fp32 out) ----------------
__global__ __launch_bounds__(256) void k_gcn_agg(const float* __restrict__ bias) {
    int n = blockIdx.x, tid = threadIdx.x;
    int s = g_start[n], e = g_start[n + 1];
    float dv = g_dinv[n];
    float2 acc[PCH];
#pragma unroll
    for (int i = 0; i < PCH; i++) {
        int f = 2 * tid + 512 * i;
        acc[i].x = (f < HFD) ? bias[f] : 0.f;
        acc[i].y = (f + 1 < HFD) ? bias[f + 1] : 0.f;
    }
    for (int p = s; p < e; p++) {
        int src = g_esrc[p];
        float coef = g_dinv[src] * dv;
        const __half2* xr = reinterpret_cast<const __half2*>(g_xw16 + (size_t)src * HFD);
#pragma unroll
        for (int i = 0; i < PCH; i++) {
            int f = 2 * tid + 512 * i;
            if (f < HFD) {
                float2 v = __half22float2(xr[f >> 1]);
                acc[i].x = fmaf(coef, v.x, acc[i].x);
                acc[i].y = fmaf(coef, v.y, acc[i].y);
            }
        }
    }
    float* o = g_h2 + (size_t)n * HFD;
#pragma unroll
    for (int i = 0; i < PCH; i++) {
        int f = 2 * tid + 512 * i;
        if (f < HFD) {   // HFD even, f even -> f+1 < HFD too
            o[f]     = fmaxf(acc[i].x, 0.f);
            o[f + 1] = fmaxf(acc[i].y, 0.f);
        }
    }
}

// ---------------- pooling fused with MLP1 A-panel split ----------------
__global__ void k_ranges(const int* __restrict__ batch) {
    int i = blockIdx.x * blockDim.x + threadIdx.x;
    if (i >= NN) return;
    int b = batch[i];
    if (b >= 0 && b < GG) {
        atomicMin(&g_pstart[b], i);
        atomicMax(&g_pend[b], i);
        atomicAdd(&g_pcnt[b], 1);
    }
}

__device__ __forceinline__ void h_split_store(__half* hi, __half* lo, float v) {
    __half h = __float2half_rn(v);
    *hi = h;
    *lo = __float2half_rn(v - __half2float(h));
}

__global__ __launch_bounds__(256) void k_pool_split() {
    int g = blockIdx.y;
    int f = blockIdx.x * blockDim.x + threadIdx.x;
    if (f >= HFD) return;
    int s = g_pstart[g], e = g_pend[g];
    float mx = -3.0e38f, sm = 0.f;
    for (int n = s; n <= e; n++) {
        float v = g_h2[(size_t)n * HFD + f];
        mx = fmaxf(mx, v);
        sm += v;
    }
    float gap = sm / (float)g_pcnt[g];
    __half* row = s_a2 + (size_t)g * (2 * KPM);
    h_split_store(&row[f],       &row[KPM + f],       mx);
    h_split_store(&row[HFD + f], &row[KPM + HFD + f], gap);
}

__global__ void k_pool_pad() {
    int g = blockIdx.x;
    int t = threadIdx.x;
    __half* row = s_a2 + (size_t)g * (2 * KPM);
    row[HF2 + t] = __float2half_rn(0.f);
    row[KPM + HF2 + t] = __float2half_rn(0.f);
}

// ---------------- launch ----------------
extern "C" void kernel_launch(void* const* d_in, const int* in_sizes, int n_in,
                              void* d_out, int out_size) {
    const float* x     = (const float*)d_in[0];
    const int*   ei    = (const int*)  d_in[1];
    const int*   batch = (const int*)  d_in[2];
    const float* W_gat = (const float*)d_in[3];
    const float* a_src = (const float*)d_in[4];
    const float* a_dst = (const float*)d_in[5];
    const float* b_gat = (const float*)d_in[6];
    const float* W_gcn = (const float*)d_in[7];
    const float* b_gcn = (const float*)d_in[8];
    const float* W1    = (const float*)d_in[9];
    const float* b1    = (const float*)d_in[10];
    const float* W2    = (const float*)d_in[11];
    const float* b2    = (const float*)d_in[12];
    const float* W3    = (const float*)d_in[13];
    const float* b3    = (const float*)d_in[14];
    float* out = (float*)d_out;

    float *p_xh, *p_h2, *p_m1, *p_m2;
    __half *p_xh16, *p_xw16, *p_a2, *p_b2;
    cudaGetSymbolAddress((void**)&p_xh,   g_xh);
    cudaGetSymbolAddress((void**)&p_xh16, g_xh16);
    cudaGetSymbolAddress((void**)&p_xw16, g_xw16);
    cudaGetSymbolAddress((void**)&p_h2,   g_h2);
    cudaGetSymbolAddress((void**)&p_m1,   g_mlp1);
    cudaGetSymbolAddress((void**)&p_m2,   g_mlp2);
    cudaGetSymbolAddress((void**)&p_a2,   s_a2);
    cudaGetSymbolAddress((void**)&p_b2,   s_b2);

    cudaFuncSetAttribute(mma_gemm<2>, cudaFuncAttributeMaxDynamicSharedMemorySize, SMEM_MMA_2);
    cudaFuncSetAttribute(mma_gemm<1>, cudaFuncAttributeMaxDynamicSharedMemorySize, SMEM_MMA_1);

    const int TM = MP_G / 128;   // 63
    const int TN = NPAD / 128;   // 54

    // ---- GEMM1 (2-term): xh = x @ W_gat; fp32 + fp16 copy; mma at launch idx 3 ----
    {
        dim3 gA((KP1 / 4 + 255) / 256, MP_G);
        k_splitA2<<<gA, 256>>>(x, p_a2, NN, FF, KP1);                 // 0
        dim3 gB(KP1 / 64, NPAD / 32);
        k_splitBT2<<<gB, dim3(32, 8)>>>(W_gat, p_b2, FF, HFD, KP1);   // 1
    }
    k_init<<<(NN + 255) / 256, 256>>>();                               // 2
    mma_gemm<2><<<TM * TN, 256, SMEM_MMA_2>>>(p_a2, p_b2, nullptr, p_xh, p_xh16,  // 3
                                              NN, HFD, HFD, KP1, TM, TN, 4);

    // CSR build + degrees
    k_count<<<(ETOT + 255) / 256, 256>>>(ei);
    k_scan<<<1, 1024>>>();
    k_scatter<<<(ETOT + 255) / 256, 256>>>(ei);
    k_dinv<<<(NN + 255) / 256, 256>>>();

    k_attn<<<NN, 320>>>(p_xh, a_src, a_dst);
    k_softmax<<<(NN + 7) / 8, dim3(32, 8)>>>();
    k_gat_agg_split<<<MP_G, 256>>>(b_gat);   // fp16 gather, writes hi-only A panel

    // ---- GEMM2 (1-term, pure fp16 A): xw16 = h @ W_gcn (fp16-only store) ----
    {
        dim3 gB(KP2 / 64, NPAD / 32);
        k_splitBT2<<<gB, dim3(32, 8)>>>(W_gcn, p_b2, HFD, HFD, KP2);
        mma_gemm<1><<<TM * TN, 256, SMEM_MMA_1>>>(p_a2, p_b2, nullptr, nullptr, p_xw16,
                                                  NN, HFD, HFD, KP2, TM, TN, 4 | 8);
    }

    k_gcn_agg<<<NN, 256>>>(b_gcn);   // fp16 gather, fp32 h2 out

    // pooling (writes MLP1 A-panel hi/lo)
    k_ranges<<<(NN + 255) / 256, 256>>>(batch);
    {
        dim3 grid((HFD + 255) / 256, GG);
        k_pool_split<<<grid, 256>>>();
        k_pool_pad<<<GG, 32>>>();
    }

    // ---- MLP1 (2-term): relu(pool @ W1 + b1) ----
    {
        dim3 gB(KPM / 64, 512 / 32);
        k_splitBT2<<<gB, dim3(32, 8)>>>(W1, p_b2, HF2, 512, KPM);
        mma_gemm<2><<<2 * 4, 256, SMEM_MMA_2>>>(p_a2, p_b2, b1, p_m1, nullptr,
                                                GG, 512, 512, KPM, 2, 4, 3);
    }

    // MLP tail (tiny)
    {
        dim3 grid(1, 2);
        sgemm<<<grid, 256>>>(p_m1, W2, b2, p_m2, GG, 128, 512, 1, 0);
    }
    {
        dim3 grid(1, 2);
        sgemm<<<grid, 256>>>(p_m2, W3, b3, out, GG, 64, 128, 1, 0);
    }
}

// round 13
// speedup vs baseline: 2.4880x; 1.0846x over previous
#include <cuda_runtime.h>
#include <cuda_fp16.h>
#include <cstdint>
#include <cstddef>

// ---------------- problem constants (fixed shapes) ----------------
#define NN    8000
#define EE    32000
#define ETOT  40000
#define GG    256
#define FF    680
#define HH    10
#define HFD   6800
#define HF2   13600

#define MP_G  8064
#define KP1   704
#define KP2   6848
#define KPM   13632
#define NPAD  6912

#define PCH   14

// ---------------- scratch ----------------
__device__ __half g_xh16[(size_t)NN * HFD];   // fp16 xh (gat gather)
__device__ __half g_xw16[(size_t)NN * HFD];   // fp16 xw (gcn gather)
__device__ float  g_h2  [(size_t)NN * HFD];
__device__ float g_wt[FF * 2 * HH];           // W-tilde [680, 20]
__device__ float g_al[NN * 2 * HH];           // logits [n, 20]: 0-9 src, 10-19 dst
__device__ float g_alpha[(size_t)ETOT * HH];
__device__ int   g_cnt[NN];
__device__ int   g_cur[NN];
__device__ int   g_start[NN + 1];
__device__ int   g_esrc[ETOT];
__device__ float g_dinv[NN];
__device__ int   g_pstart[GG];
__device__ int   g_pend[GG];
__device__ int   g_pcnt[GG];
__device__ float g_mlp1[GG * 512];
__device__ float g_mlp2[GG * 128];

// fp16 panels
__device__ __half s_a2[(size_t)MP_G * (2 * KP2)];
__device__ __half s_b2[(size_t)NPAD * (2 * KP2)];

// ---------------- PTX helpers ----------------
__device__ __forceinline__ uint32_t smem_u32(const void* p) {
    uint32_t a;
    asm("{ .reg .u64 t; cvta.to.shared.u64 t, %1; cvt.u32.u64 %0, t; }" : "=r"(a) : "l"(p));
    return a;
}

__device__ __forceinline__ void cp16(uint32_t dst, const void* src) {
    asm volatile("cp.async.cg.shared.global [%0], [%1], 16;" :: "r"(dst), "l"(src));
}
#define CP_COMMIT() asm volatile("cp.async.commit_group;" ::: "memory")
__device__ __forceinline__ void cp_wait(int pend) {
    if (pend <= 0)      asm volatile("cp.async.wait_group 0;" ::: "memory");
    else                asm volatile("cp.async.wait_group 1;" ::: "memory");
}

__device__ __forceinline__ void ldsm4(uint32_t* r, uint32_t addr) {
    asm volatile("ldmatrix.sync.aligned.m8n8.x4.shared.b16 {%0,%1,%2,%3}, [%4];"
                 : "=r"(r[0]), "=r"(r[1]), "=r"(r[2]), "=r"(r[3]) : "r"(addr));
}

__device__ __forceinline__ void mma_f32acc(float* d, const uint32_t* a, uint32_t b0, uint32_t b1) {
    asm volatile("mma.sync.aligned.m16n8k16.row.col.f32.f16.f16.f32 "
                 "{%0,%1,%2,%3}, {%4,%5,%6,%7}, {%8,%9}, {%0,%1,%2,%3};"
                 : "+f"(d[0]), "+f"(d[1]), "+f"(d[2]), "+f"(d[3])
                 : "r"(a[0]), "r"(a[1]), "r"(a[2]), "r"(a[3]), "r"(b0), "r"(b1));
}

__device__ __forceinline__ uint32_t sm_tile_off(int row, int chunk) {
    return (uint32_t)(row * 64 + ((chunk ^ ((row >> 1) & 3)) << 4));
}

// ---------------- fp16 GEMM, TERMS = 1 or 2, optional split-K ----------------
// flags: 1=bias, 2=relu, 4=store fp16 to C16, 8=skip fp32 store, 16=atomicAdd fp32
#define BM 128
#define BN 128
#define BK 32
#define STG 3
#define SUB_BYTES 8192
#define SMEM_MMA_2 (STG * 3 * SUB_BYTES)   // 72KB
#define SMEM_MMA_1 (STG * 2 * SUB_BYTES)   // 48KB

template<int TERMS>
__global__ __launch_bounds__(256, 2) void mma_gemm(
    const __half* __restrict__ A2, const __half* __restrict__ B2,
    const float* __restrict__ bias, float* __restrict__ C, __half* __restrict__ C16,
    int M, int N, int ldc, int KP, int tiles_m, int tiles_n, int flags, int csplit)
{
    constexpr int STAGE_BYTES = (TERMS + 1) * SUB_BYTES;
    extern __shared__ char smem[];
    uint32_t sb = smem_u32(smem);
    const int tid = threadIdx.x;
    const int wid = tid >> 5;
    const int lane = tid & 31;
    const int warp_m = wid & 3;
    const int warp_n = wid >> 2;

    int gm, gn;
    {
        const int GM = 8;
        int bid = blockIdx.x;
        int per = GM * tiles_n;
        int grp = bid / per;
        int fm  = grp * GM;
        int gsz = tiles_m - fm; if (gsz > GM) gsz = GM;
        int r = bid - grp * per;
        gm = fm + r % gsz;
        gn = r / gsz;
    }

    const int CH = KP / BK;
    int c0 = blockIdx.y * csplit;
    int c1 = c0 + csplit; if (c1 > CH) c1 = CH;
    const int L = c1 - c0;
    const int KA = TERMS * KP;

    const int lrow = tid >> 1;
    const int lc0  = (tid & 1) * 2;
    const __half* pA = A2 + (size_t)(gm * BM + lrow) * KA + lc0 * 8 + c0 * BK;
    const __half* pB = B2 + (size_t)(gn * BN + lrow) * KP + lc0 * 8 + c0 * BK;
    const uint32_t so0 = sm_tile_off(lrow, lc0);
    const uint32_t so1 = so0 ^ 16;

    const uint32_t aoff00 = sm_tile_off(warp_m * 32 + (lane & 15), (lane >> 4));
    const uint32_t boff00 = TERMS * SUB_BYTES + sm_tile_off(warp_n * 64 + (lane & 15), (lane >> 4));

    float acc[2][8][4];
#pragma unroll
    for (int mi = 0; mi < 2; mi++)
#pragma unroll
        for (int ni = 0; ni < 8; ni++)
#pragma unroll
            for (int j = 0; j < 4; j++) acc[mi][ni][j] = 0.f;

#pragma unroll
    for (int c = 0; c < 2; c++) {
        if (c >= L) break;
        uint32_t stb = sb + c * STAGE_BYTES;
        int ko = c * BK;
        cp16(stb + so0, pA + ko);
        cp16(stb + so1, pA + ko + 8);
        if (TERMS == 2) {
            cp16(stb + SUB_BYTES + so0, pA + KP + ko);
            cp16(stb + SUB_BYTES + so1, pA + KP + ko + 8);
        }
        cp16(stb + TERMS * SUB_BYTES + so0, pB + ko);
        cp16(stb + TERMS * SUB_BYTES + so1, pB + ko + 8);
        CP_COMMIT();
    }

    int s = 0;
    int sload = 2;
    for (int c = 0; c < L; c++) {
        cp_wait((L - 1 - c) >= 1 ? 1 : 0);
        __syncthreads();

        if (c + 2 < L) {
            uint32_t dtb = sb + sload * STAGE_BYTES;
            int ko = (c + 2) * BK;
            cp16(dtb + so0, pA + ko);
            cp16(dtb + so1, pA + ko + 8);
            if (TERMS == 2) {
                cp16(dtb + SUB_BYTES + so0, pA + KP + ko);
                cp16(dtb + SUB_BYTES + so1, pA + KP + ko + 8);
            }
            cp16(dtb + TERMS * SUB_BYTES + so0, pB + ko);
            cp16(dtb + TERMS * SUB_BYTES + so1, pB + ko + 8);
            CP_COMMIT();
        }

        uint32_t stb = sb + s * STAGE_BYTES;
#pragma unroll
        for (int ks = 0; ks < 2; ks++) {
            uint32_t ao = stb + (aoff00 ^ (ks * 32));
            uint32_t bo = stb + (boff00 ^ (ks * 32));
            uint32_t ahi[2][4], alo[2][4], bfr[4][4];
            ldsm4(ahi[0], ao);
            ldsm4(ahi[1], ao + 1024);
            if (TERMS == 2) {
                ldsm4(alo[0], ao + SUB_BYTES);
                ldsm4(alo[1], ao + SUB_BYTES + 1024);
            }
#pragma unroll
            for (int g = 0; g < 4; g++) ldsm4(bfr[g], bo + g * 1024);
#pragma unroll
            for (int g = 0; g < 4; g++)
#pragma unroll
                for (int h = 0; h < 2; h++)
#pragma unroll
                    for (int mi = 0; mi < 2; mi++)
                        mma_f32acc(acc[mi][g * 2 + h], ahi[mi], bfr[g][h], bfr[g][h + 2]);
            if (TERMS == 2) {
#pragma unroll
                for (int g = 0; g < 4; g++)
#pragma unroll
                    for (int h = 0; h < 2; h++)
#pragma unroll
                        for (int mi = 0; mi < 2; mi++)
                            mma_f32acc(acc[mi][g * 2 + h], alo[mi], bfr[g][h], bfr[g][h + 2]);
            }
        }
        s++; if (s == STG) s = 0;
        sload++; if (sload == STG) sload = 0;
    }

    // epilogue
    int erow0 = gm * BM + warp_m * 32 + (lane >> 2);
    int ecol0 = gn * BN + warp_n * 64 + (lane & 3) * 2;
#pragma unroll
    for (int mi = 0; mi < 2; mi++) {
#pragma unroll
        for (int ni = 0; ni < 8; ni++) {
            int r = erow0 + mi * 16;
            int cc = ecol0 + ni * 8;
#pragma unroll
            for (int half_i = 0; half_i < 2; half_i++) {
                int rr = r + half_i * 8;
                if (rr < M && cc < N) {
                    float o0 = acc[mi][ni][half_i * 2 + 0];
                    float o1 = acc[mi][ni][half_i * 2 + 1];
                    size_t idx = (size_t)rr * ldc + cc;
                    if (flags & 16) {
                        atomicAdd(&C[idx], o0);
                        atomicAdd(&C[idx + 1], o1);
                    } else {
                        if (flags & 1) { o0 += bias[cc]; o1 += bias[cc + 1]; }
                        if (flags & 2) { o0 = fmaxf(o0, 0.f); o1 = fmaxf(o1, 0.f); }
                        if (!(flags & 8)) { C[idx] = o0; C[idx + 1] = o1; }
                        if (flags & 4)
                            *reinterpret_cast<__half2*>(&C16[idx]) = __floats2half2_rn(o0, o1);
                    }
                }
            }
        }
    }
}

// ---------------- conversion kernels ----------------
__device__ __forceinline__ uint32_t pack_h2(__half a, __half b) {
    return ((uint32_t)__half_as_ushort(b) << 16) | __half_as_ushort(a);
}

__global__ void k_splitA2(const float* __restrict__ src, __half* __restrict__ dst,
                          int M, int K, int KP)
{
    int k = (blockIdx.x * 256 + threadIdx.x) * 4;
    int m = blockIdx.y;
    if (k >= KP) return;
    float4 v = make_float4(0.f, 0.f, 0.f, 0.f);
    if (m < M && k < K) v = *reinterpret_cast<const float4*>(&src[(size_t)m * K + k]);
    __half h0 = __float2half_rn(v.x), h1 = __float2half_rn(v.y);
    __half h2 = __float2half_rn(v.z), h3 = __float2half_rn(v.w);
    __half l0 = __float2half_rn(v.x - __half2float(h0));
    __half l1 = __float2half_rn(v.y - __half2float(h1));
    __half l2 = __float2half_rn(v.z - __half2float(h2));
    __half l3 = __float2half_rn(v.w - __half2float(h3));
    uint2 hp, lp;
    hp.x = pack_h2(h0, h1); hp.y = pack_h2(h2, h3);
    lp.x = pack_h2(l0, l1); lp.y = pack_h2(l2, l3);
    size_t base = (size_t)m * (2 * KP);
    *reinterpret_cast<uint2*>(&dst[base + k]) = hp;
    *reinterpret_cast<uint2*>(&dst[base + KP + k]) = lp;
}

__global__ void k_splitBT2(const float* __restrict__ src, __half* __restrict__ dst,
                           int K, int N, int KP)
{
    __shared__ float t[64][33];
    int k0 = blockIdx.x * 64, n0 = blockIdx.y * 32;
    int tx = threadIdx.x, ty = threadIdx.y;
#pragma unroll
    for (int it = 0; it < 8; it++) {
        int k = k0 + ty + it * 8;
        int n = n0 + tx;
        t[ty + it * 8][tx] = (k < K && n < N) ? src[(size_t)k * N + n] : 0.f;
    }
    __syncthreads();
    int uid = ty * 32 + tx;
    int nl = uid >> 3;
    int kg = (uid & 7) * 8;
    size_t base = (size_t)(n0 + nl) * KP + k0;
#pragma unroll
    for (int q = 0; q < 4; q++) {
        int kk = kg + q * 2;
        float v0 = t[kk][nl], v1 = t[kk + 1][nl];
        *reinterpret_cast<uint32_t*>(&dst[base + kk]) =
            pack_h2(__float2half_rn(v0), __float2half_rn(v1));
    }
}

// ---------------- scalar SGEMM ----------------
__global__ __launch_bounds__(256) void sgemm(const float* __restrict__ A,
                                             const float* __restrict__ B,
                                             const float* __restrict__ bias,
                                             float* __restrict__ C,
                                             int M, int N, int K,
                                             int hasBias, int doRelu) {
    __shared__ float As[8][128];
    __shared__ float Bs[8][128];
    const int tid   = threadIdx.x;
    const int tileM = blockIdx.y * 128;
    const int tileN = blockIdx.x * 128;

    const int aRow = tid >> 1;
    const int aK4  = (tid & 1) * 4;
    const int bRow = tid >> 5;
    const int bCol = (tid & 31) * 4;
    const int ty   = tid >> 4;
    const int tx   = tid & 15;

    float acc[8][8];
#pragma unroll
    for (int i = 0; i < 8; i++)
#pragma unroll
        for (int j = 0; j < 8; j++) acc[i][j] = 0.f;

    for (int k0 = 0; k0 < K; k0 += 8) {
        float4 av = make_float4(0.f, 0.f, 0.f, 0.f);
        int gr = tileM + aRow;
        if (gr < M) av = *reinterpret_cast<const float4*>(&A[(size_t)gr * K + k0 + aK4]);
        As[aK4 + 0][aRow] = av.x;
        As[aK4 + 1][aRow] = av.y;
        As[aK4 + 2][aRow] = av.z;
        As[aK4 + 3][aRow] = av.w;

        float4 bv = make_float4(0.f, 0.f, 0.f, 0.f);
        int gc = tileN + bCol;
        const float* bp = &B[(size_t)(k0 + bRow) * N + gc];
        if (gc + 3 < N) {
            bv = *reinterpret_cast<const float4*>(bp);
        } else {
            if (gc + 0 < N) bv.x = bp[0];
            if (gc + 1 < N) bv.y = bp[1];
            if (gc + 2 < N) bv.z = bp[2];
            if (gc + 3 < N) bv.w = bp[3];
        }
        *reinterpret_cast<float4*>(&Bs[bRow][bCol]) = bv;

        __syncthreads();
#pragma unroll
        for (int kk = 0; kk < 8; kk++) {
            float a[8], b[8];
            *reinterpret_cast<float4*>(&a[0]) = *reinterpret_cast<float4*>(&As[kk][ty * 8]);
            *reinterpret_cast<float4*>(&a[4]) = *reinterpret_cast<float4*>(&As[kk][ty * 8 + 4]);
            *reinterpret_cast<float4*>(&b[0]) = *reinterpret_cast<float4*>(&Bs[kk][tx * 8]);
            *reinterpret_cast<float4*>(&b[4]) = *reinterpret_cast<float4*>(&Bs[kk][tx * 8 + 4]);
#pragma unroll
            for (int i = 0; i < 8; i++)
#pragma unroll
                for (int j = 0; j < 8; j++) acc[i][j] = fmaf(a[i], b[j], acc[i][j]);
        }
        __syncthreads();
    }

#pragma unroll
    for (int i = 0; i < 8; i++) {
        int row = tileM + ty * 8 + i;
        if (row >= M) continue;
#pragma unroll
        for (int j = 0; j < 8; j++) {
            int col = tileN + tx * 8 + j;
            if (col < N) {
                float v = acc[i][j];
                if (hasBias) v += bias[col];
                if (doRelu) v = fmaxf(v, 0.f);
                C[(size_t)row * N + col] = v;
            }
        }
    }
}

// ---------------- attention pre-projection ----------------
// W~[i, h] = sum_f W_gat[i, h*FF+f] * a_s[h*FF+f]; cols 10-19 use a_d.
__global__ void k_wtilde(const float* __restrict__ W, const float* __restrict__ a_s,
                         const float* __restrict__ a_d) {
    int i = blockIdx.x;
    int w = threadIdx.x >> 5;
    int lane = threadIdx.x & 31;
    if (w >= HH) return;
    const float* row = W + (size_t)i * HFD + w * FF;
    const float* as  = a_s + w * FF;
    const float* ad  = a_d + w * FF;
    float s1 = 0.f, s2 = 0.f;
    for (int f = lane; f < FF; f += 32) {
        float v = row[f];
        s1 = fmaf(v, as[f], s1);
        s2 = fmaf(v, ad[f], s2);
    }
#pragma unroll
    for (int o = 16; o; o >>= 1) {
        s1 += __shfl_down_sync(0xffffffffu, s1, o);
        s2 += __shfl_down_sync(0xffffffffu, s2, o);
    }
    if (lane == 0) { g_wt[i * 20 + w] = s1; g_wt[i * 20 + 10 + w] = s2; }
}

// ---------------- MLP1 bias-fill + relu ----------------
__global__ void k_fill_bias512(float* __restrict__ dst, const float* __restrict__ bias) {
    int i = blockIdx.x * 256 + threadIdx.x;
    if (i < GG * 512) dst[i] = bias[i & 511];
}
__global__ void k_relu_small(float* __restrict__ a, int n) {
    int i = blockIdx.x * 256 + threadIdx.x;
    if (i < n) a[i] = fmaxf(a[i], 0.f);
}

// ---------------- CSR build ----------------
__global__ void k_init() {
    int i = blockIdx.x * blockDim.x + threadIdx.x;
    if (i < NN) { g_cnt[i] = 0; g_cur[i] = 0; }
    if (i < GG) { g_pstart[i] = 0x7fffffff; g_pend[i] = -1; g_pcnt[i] = 0; }
}

__global__ void k_count(const int* __restrict__ ei) {
    int k = blockIdx.x * blockDim.x + threadIdx.x;
    if (k >= ETOT) return;
    int dst = (k < EE) ? ei[EE + k] : (k - EE);
    atomicAdd(&g_cnt[dst], 1);
}

__global__ __launch_bounds__(1024) void k_scan() {
    __shared__ int sd[1024];
    __shared__ int scarry;
    int tid = threadIdx.x;
    if (tid == 0) { scarry = 0; g_start[0] = 0; }
    __syncthreads();
    for (int base = 0; base < NN; base += 1024) {
        int v = (base + tid < NN) ? g_cnt[base + tid] : 0;
        sd[tid] = v;
        __syncthreads();
        for (int o = 1; o < 1024; o <<= 1) {
            int t = (tid >= o) ? sd[tid - o] : 0;
            __syncthreads();
            sd[tid] += t;
            __syncthreads();
        }
        int run = scarry;
        if (base + tid < NN) g_start[base + tid + 1] = run + sd[tid];
        __syncthreads();
        if (tid == 1023) scarry = run + sd[1023];
        __syncthreads();
    }
}

__global__ void k_scatter(const int* __restrict__ ei) {
    int k = blockIdx.x * blockDim.x + threadIdx.x;
    if (k >= ETOT) return;
    int src = (k < EE) ? ei[k]      : (k - EE);
    int dst = (k < EE) ? ei[EE + k] : (k - EE);
    int pos = g_start[dst] + atomicAdd(&g_cur[dst], 1);
    g_esrc[pos] = src;
}

__global__ void k_dinv() {
    int i = blockIdx.x * blockDim.x + threadIdx.x;
    if (i < NN) g_dinv[i] = rsqrtf((float)g_cnt[i]);
}

// ---------------- softmax (g_al layout: [n, 20], src 0-9, dst 10-19) ----------------
__global__ void k_softmax() {
    int node = blockIdx.x * blockDim.y + threadIdx.y;
    if (node >= NN) return;
    int lane = threadIdx.x;
    bool act = lane < HH;
    int s = g_start[node], e = g_start[node + 1];
    float ald_v = act ? g_al[node * 20 + 10 + lane] : 0.f;
    float mx = -3.0e38f;
    for (int p = s; p < e; p++) {
        int src = g_esrc[p];
        if (act) {
            float v = g_al[src * 20 + lane] + ald_v;
            v = fmaxf(v, 0.2f * v);
            mx = fmaxf(mx, v);
        }
    }
    float z = 0.f;
    for (int p = s; p < e; p++) {
        int src = g_esrc[p];
        if (act) {
            float v = g_al[src * 20 + lane] + ald_v;
            v = fmaxf(v, 0.2f * v);
            float ex = expf(v - mx);
            g_alpha[(size_t)p * HH + lane] = ex;
            z += ex;
        }
    }
    float inv = 1.f / (z + 1e-16f);
    for (int p = s; p < e; p++)
        if (act) g_alpha[(size_t)p * HH + lane] *= inv;
}

// ---------------- GAT aggregation (fp16 gather) -> hi-only fp16 A panel ----------------
__global__ __launch_bounds__(256) void k_gat_agg_split(const float* __restrict__ bias) {
    int n = blockIdx.x, tid = threadIdx.x;
    __half* arow = s_a2 + (size_t)n * KP2;
    if (n >= NN) {
        for (int k = tid; k < KP2 / 2; k += 256)
            reinterpret_cast<uint32_t*>(arow)[k] = 0;
        return;
    }
    int s = g_start[n], e = g_start[n + 1];
    float2 acc[PCH];
    int hidx[PCH];
#pragma unroll
    for (int i = 0; i < PCH; i++) {
        int f = 2 * tid + 512 * i;
        hidx[i] = (f < HFD) ? (f / FF) : 0;
        acc[i].x = (f < HFD) ? bias[f] : 0.f;
        acc[i].y = (f + 1 < HFD) ? bias[f + 1] : 0.f;
    }
    for (int p = s; p < e; p++) {
        int src = g_esrc[p];
        const __half2* xr = reinterpret_cast<const __half2*>(g_xh16 + (size_t)src * HFD);
        const float* al = g_alpha + (size_t)p * HH;
#pragma unroll
        for (int i = 0; i < PCH; i++) {
            int f = 2 * tid + 512 * i;
            if (f < HFD) {
                float2 v = __half22float2(xr[f >> 1]);
                float a = al[hidx[i]];
                acc[i].x = fmaf(a, v.x, acc[i].x);
                acc[i].y = fmaf(a, v.y, acc[i].y);
            }
        }
    }
#pragma unroll
    for (int i = 0; i < PCH; i++) {
        int f = 2 * tid + 512 * i;
        if (f < KP2) {
            float vx = (f < HFD) ? fmaxf(acc[i].x, 0.f) : 0.f;
            float vy = (f + 1 < HFD) ? fmaxf(acc[i].y, 0.f) : 0.f;
            *reinterpret_cast<uint32_t*>(&arow[f]) =
                pack_h2(__float2half_rn(vx), __float2half_rn(vy));
        }
    }
}

// ---------------- GCN aggregation (fp16 gather, fp32 out) ----------------
__global__ __launch_bounds__(256) void k_gcn_agg(const float* __restrict__ bias) {
    int n = blockIdx.x, tid = threadIdx.x;
    int s = g_start[n], e = g_start[n + 1];
    float dv = g_dinv[n];
    float2 acc[PCH];
#pragma unroll
    for (int i = 0; i < PCH; i++) {
        int f = 2 * tid + 512 * i;
        acc[i].x = (f < HFD) ? bias[f] : 0.f;
        acc[i].y = (f + 1 < HFD) ? bias[f + 1] : 0.f;
    }
    for (int p = s; p < e; p++) {
        int src = g_esrc[p];
        float coef = g_dinv[src] * dv;
        const __half2* xr = reinterpret_cast<const __half2*>(g_xw16 + (size_t)src * HFD);
#pragma unroll
        for (int i = 0; i < PCH; i++) {
            int f = 2 * tid + 512 * i;
            if (f < HFD) {
                float2 v = __half22float2(xr[f >> 1]);
                acc[i].x = fmaf(coef, v.x, acc[i].x);
                acc[i].y = fmaf(coef, v.y, acc[i].y);
            }
        }
    }
    float* o = g_h2 + (size_t)n * HFD;
#pragma unroll
    for (int i = 0; i < PCH; i++) {
        int f = 2 * tid + 512 * i;
        if (f < HFD) {
            o[f]     = fmaxf(acc[i].x, 0.f);
            o[f + 1] = fmaxf(acc[i].y, 0.f);
        }
    }
}

// ---------------- pooling fused with MLP1 A-panel split ----------------
__global__ void k_ranges(const int* __restrict__ batch) {
    int i = blockIdx.x * blockDim.x + threadIdx.x;
    if (i >= NN) return;
    int b = batch[i];
    if (b >= 0 && b < GG) {
        atomicMin(&g_pstart[b], i);
        atomicMax(&g_pend[b], i);
        atomicAdd(&g_pcnt[b], 1);
    }
}

__device__ __forceinline__ void h_split_store(__half* hi, __half* lo, float v) {
    __half h = __float2half_rn(v);
    *hi = h;
    *lo = __float2half_rn(v - __half2float(h));
}

__global__ __launch_bounds__(256) void k_pool_split() {
    int g = blockIdx.y;
    int f = blockIdx.x * blockDim.x + threadIdx.x;
    if (f >= HFD) return;
    int s = g_pstart[g], e = g_pend[g];
    float mx = -3.0e38f, sm = 0.f;
    for (int n = s; n <= e; n++) {
        float v = g_h2[(size_t)n * HFD + f];
        mx = fmaxf(mx, v);
        sm += v;
    }
    float gap = sm / (float)g_pcnt[g];
    __half* row = s_a2 + (size_t)g * (2 * KPM);
    h_split_store(&row[f],       &row[KPM + f],       mx);
    h_split_store(&row[HFD + f], &row[KPM + HFD + f], gap);
}

__global__ void k_pool_pad() {
    int g = blockIdx.x;
    int t = threadIdx.x;
    __half* row = s_a2 + (size_t)g * (2 * KPM);
    row[HF2 + t] = __float2half_rn(0.f);
    row[KPM + HF2 + t] = __float2half_rn(0.f);
}

// ---------------- launch ----------------
extern "C" void kernel_launch(void* const* d_in, const int* in_sizes, int n_in,
                              void* d_out, int out_size) {
    const float* x     = (const float*)d_in[0];
    const int*   ei    = (const int*)  d_in[1];
    const int*   batch = (const int*)  d_in[2];
    const float* W_gat = (const float*)d_in[3];
    const float* a_src = (const float*)d_in[4];
    const float* a_dst = (const float*)d_in[5];
    const float* b_gat = (const float*)d_in[6];
    const float* W_gcn = (const float*)d_in[7];
    const float* b_gcn = (const float*)d_in[8];
    const float* W1    = (const float*)d_in[9];
    const float* b1    = (const float*)d_in[10];
    const float* W2    = (const float*)d_in[11];
    const float* b2    = (const float*)d_in[12];
    const float* W3    = (const float*)d_in[13];
    const float* b3    = (const float*)d_in[14];
    float* out = (float*)d_out;

    float *p_wt, *p_al, *p_m1, *p_m2;
    __half *p_xh16, *p_xw16, *p_a2, *p_b2;
    cudaGetSymbolAddress((void**)&p_wt,   g_wt);
    cudaGetSymbolAddress((void**)&p_al,   g_al);
    cudaGetSymbolAddress((void**)&p_xh16, g_xh16);
    cudaGetSymbolAddress((void**)&p_xw16, g_xw16);
    cudaGetSymbolAddress((void**)&p_m1,   g_mlp1);
    cudaGetSymbolAddress((void**)&p_m2,   g_mlp2);
    cudaGetSymbolAddress((void**)&p_a2,   s_a2);
    cudaGetSymbolAddress((void**)&p_b2,   s_b2);

    cudaFuncSetAttribute(mma_gemm<2>, cudaFuncAttributeMaxDynamicSharedMemorySize, SMEM_MMA_2);
    cudaFuncSetAttribute(mma_gemm<1>, cudaFuncAttributeMaxDynamicSharedMemorySize, SMEM_MMA_1);

    const int TM = MP_G / 128;   // 63
    const int TN = NPAD / 128;   // 54

    // ---- GEMM1 (2-term): xh16 = x @ W_gat (fp16-only); mma at launch idx 3 ----
    {
        dim3 gA((KP1 / 4 + 255) / 256, MP_G);
        k_splitA2<<<gA, 256>>>(x, p_a2, NN, FF, KP1);                 // 0
        dim3 gB(KP1 / 64, NPAD / 32);
        k_splitBT2<<<gB, dim3(32, 8)>>>(W_gat, p_b2, FF, HFD, KP1);   // 1
    }
    k_init<<<(NN + 255) / 256, 256>>>();                               // 2
    mma_gemm<2><<<TM * TN, 256, SMEM_MMA_2>>>(p_a2, p_b2, nullptr, nullptr, p_xh16,  // 3
                                              NN, HFD, HFD, KP1, TM, TN, 4 | 8, KP1 / 32);

    // attention logits via pre-projection: g_al = x @ W~ (exact fp32 path)
    k_wtilde<<<FF, 320>>>(W_gat, a_src, a_dst);
    {
        dim3 grid(1, (NN + 127) / 128);
        sgemm<<<grid, 256>>>(x, p_wt, nullptr, p_al, NN, 20, FF, 0, 0);
    }

    // CSR build + degrees
    k_count<<<(ETOT + 255) / 256, 256>>>(ei);
    k_scan<<<1, 1024>>>();
    k_scatter<<<(ETOT + 255) / 256, 256>>>(ei);
    k_dinv<<<(NN + 255) / 256, 256>>>();

    k_softmax<<<(NN + 7) / 8, dim3(32, 8)>>>();
    k_gat_agg_split<<<MP_G, 256>>>(b_gat);

    // ---- GEMM2 (1-term): xw16 = h @ W_gcn (fp16-only store) ----
    {
        dim3 gB(KP2 / 64, NPAD / 32);
        k_splitBT2<<<gB, dim3(32, 8)>>>(W_gcn, p_b2, HFD, HFD, KP2);
        mma_gemm<1><<<TM * TN, 256, SMEM_MMA_1>>>(p_a2, p_b2, nullptr, nullptr, p_xw16,
                                                  NN, HFD, HFD, KP2, TM, TN, 4 | 8, KP2 / 32);
    }

    k_gcn_agg<<<NN, 256>>>(b_gcn);

    // pooling (writes MLP1 A-panel hi/lo)
    k_ranges<<<(NN + 255) / 256, 256>>>(batch);
    {
        dim3 grid((HFD + 255) / 256, GG);
        k_pool_split<<<grid, 256>>>();
        k_pool_pad<<<GG, 32>>>();
    }

    // ---- MLP1 (2-term, split-K): g_mlp1 = relu(pool @ W1 + b1) ----
    {
        dim3 gB(KPM / 64, 512 / 32);
        k_splitBT2<<<gB, dim3(32, 8)>>>(W1, p_b2, HF2, 512, KPM);
        k_fill_bias512<<<(GG * 512 + 255) / 256, 256>>>(p_m1, b1);
        // CH = 426; 16 splits of 27 chunks
        mma_gemm<2><<<dim3(2 * 4, 16), 256, SMEM_MMA_2>>>(p_a2, p_b2, nullptr, p_m1, nullptr,
                                                          GG, 512, 512, KPM, 2, 4, 16, 27);
        k_relu_small<<<(GG * 512 + 255) / 256, 256>>>(p_m1, GG * 512);
    }

    // MLP tail (tiny)
    {
        dim3 grid(1, 2);
        sgemm<<<grid, 256>>>(p_m1, W2, b2, p_m2, GG, 128, 512, 1, 0);
    }
    {
        dim3 grid(1, 2);
        sgemm<<<grid, 256>>>(p_m2, W3, b3, out, GG, 64, 128, 1, 0);
    }
}

// round 14
// speedup vs baseline: 2.6764x; 1.0757x over previous
#include <cuda_runtime.h>
#include <cuda_fp16.h>
#include <cstdint>
#include <cstddef>

// ---------------- problem constants (fixed shapes) ----------------
#define NN    8000
#define EE    32000
#define ETOT  40000
#define GG    256
#define FF    680
#define HH    10
#define HFD   6800
#define HF2   13600

#define MP_G  8064
#define KP1   704
#define KP2   6848
#define KPM   13632
#define NPAD  6912

#define PCH   14

// ---------------- scratch ----------------
__device__ __half g_xh16[(size_t)NN * HFD];   // fp16 xh (gat gather)
__device__ __half g_xw16[(size_t)NN * HFD];   // fp16 xw (gcn gather)
__device__ __half g_h216[(size_t)NN * HFD];   // fp16 gcn output (pool input)
__device__ float g_wt[FF * 2 * HH];           // W-tilde [680, 20]
__device__ float g_al[NN * 2 * HH];           // logits [n, 20]: 0-9 src, 10-19 dst
__device__ float g_alpha[(size_t)ETOT * HH];
__device__ int   g_cnt[NN];
__device__ int   g_cur[NN];
__device__ int   g_start[NN + 1];
__device__ int   g_esrc[ETOT];
__device__ float g_dinv[NN];
__device__ int   g_pstart[GG];
__device__ int   g_pend[GG];
__device__ int   g_pcnt[GG];
__device__ float g_mlp1[GG * 512];
__device__ float g_mlp2[GG * 128];

// fp16 panels
__device__ __half s_a2[(size_t)MP_G * (2 * KP2)];
__device__ __half s_b2[(size_t)NPAD * (2 * KP2)];

// ---------------- PTX helpers ----------------
__device__ __forceinline__ uint32_t smem_u32(const void* p) {
    uint32_t a;
    asm("{ .reg .u64 t; cvta.to.shared.u64 t, %1; cvt.u32.u64 %0, t; }" : "=r"(a) : "l"(p));
    return a;
}

__device__ __forceinline__ void cp16(uint32_t dst, const void* src) {
    asm volatile("cp.async.cg.shared.global [%0], [%1], 16;" :: "r"(dst), "l"(src));
}
#define CP_COMMIT() asm volatile("cp.async.commit_group;" ::: "memory")
__device__ __forceinline__ void cp_wait(int pend) {
    if (pend <= 0)      asm volatile("cp.async.wait_group 0;" ::: "memory");
    else                asm volatile("cp.async.wait_group 1;" ::: "memory");
}

__device__ __forceinline__ void ldsm4(uint32_t* r, uint32_t addr) {
    asm volatile("ldmatrix.sync.aligned.m8n8.x4.shared.b16 {%0,%1,%2,%3}, [%4];"
                 : "=r"(r[0]), "=r"(r[1]), "=r"(r[2]), "=r"(r[3]) : "r"(addr));
}

__device__ __forceinline__ void mma_f32acc(float* d, const uint32_t* a, uint32_t b0, uint32_t b1) {
    asm volatile("mma.sync.aligned.m16n8k16.row.col.f32.f16.f16.f32 "
                 "{%0,%1,%2,%3}, {%4,%5,%6,%7}, {%8,%9}, {%0,%1,%2,%3};"
                 : "+f"(d[0]), "+f"(d[1]), "+f"(d[2]), "+f"(d[3])
                 : "r"(a[0]), "r"(a[1]), "r"(a[2]), "r"(a[3]), "r"(b0), "r"(b1));
}

__device__ __forceinline__ uint32_t sm_tile_off(int row, int chunk) {
    return (uint32_t)(row * 64 + ((chunk ^ ((row >> 1) & 3)) << 4));
}

// ---------------- fp16 GEMM, TERMS = 1 or 2, optional split-K ----------------
// flags: 1=bias, 2=relu, 4=store fp16 to C16, 8=skip fp32 store, 16=atomicAdd fp32
#define BM 128
#define BN 128
#define BK 32
#define STG 3
#define SUB_BYTES 8192
#define SMEM_MMA_2 (STG * 3 * SUB_BYTES)   // 72KB
#define SMEM_MMA_1 (STG * 2 * SUB_BYTES)   // 48KB

template<int TERMS>
__global__ __launch_bounds__(256, 2) void mma_gemm(
    const __half* __restrict__ A2, const __half* __restrict__ B2,
    const float* __restrict__ bias, float* __restrict__ C, __half* __restrict__ C16,
    int M, int N, int ldc, int KP, int tiles_m, int tiles_n, int flags, int csplit)
{
    constexpr int STAGE_BYTES = (TERMS + 1) * SUB_BYTES;
    extern __shared__ char smem[];
    uint32_t sb = smem_u32(smem);
    const int tid = threadIdx.x;
    const int wid = tid >> 5;
    const int lane = tid & 31;
    const int warp_m = wid & 3;
    const int warp_n = wid >> 2;

    int gm, gn;
    {
        const int GM = 8;
        int bid = blockIdx.x;
        int per = GM * tiles_n;
        int grp = bid / per;
        int fm  = grp * GM;
        int gsz = tiles_m - fm; if (gsz > GM) gsz = GM;
        int r = bid - grp * per;
        gm = fm + r % gsz;
        gn = r / gsz;
    }

    const int CH = KP / BK;
    int c0 = blockIdx.y * csplit;
    int c1 = c0 + csplit; if (c1 > CH) c1 = CH;
    const int L = c1 - c0;
    const int KA = TERMS * KP;

    const int lrow = tid >> 1;
    const int lc0  = (tid & 1) * 2;
    const __half* pA = A2 + (size_t)(gm * BM + lrow) * KA + lc0 * 8 + c0 * BK;
    const __half* pB = B2 + (size_t)(gn * BN + lrow) * KP + lc0 * 8 + c0 * BK;
    const uint32_t so0 = sm_tile_off(lrow, lc0);
    const uint32_t so1 = so0 ^ 16;

    const uint32_t aoff00 = sm_tile_off(warp_m * 32 + (lane & 15), (lane >> 4));
    const uint32_t boff00 = TERMS * SUB_BYTES + sm_tile_off(warp_n * 64 + (lane & 15), (lane >> 4));

    float acc[2][8][4];
#pragma unroll
    for (int mi = 0; mi < 2; mi++)
#pragma unroll
        for (int ni = 0; ni < 8; ni++)
#pragma unroll
            for (int j = 0; j < 4; j++) acc[mi][ni][j] = 0.f;

#pragma unroll
    for (int c = 0; c < 2; c++) {
        if (c >= L) break;
        uint32_t stb = sb + c * STAGE_BYTES;
        int ko = c * BK;
        cp16(stb + so0, pA + ko);
        cp16(stb + so1, pA + ko + 8);
        if (TERMS == 2) {
            cp16(stb + SUB_BYTES + so0, pA + KP + ko);
            cp16(stb + SUB_BYTES + so1, pA + KP + ko + 8);
        }
        cp16(stb + TERMS * SUB_BYTES + so0, pB + ko);
        cp16(stb + TERMS * SUB_BYTES + so1, pB + ko + 8);
        CP_COMMIT();
    }

    int s = 0;
    int sload = 2;
    for (int c = 0; c < L; c++) {
        cp_wait((L - 1 - c) >= 1 ? 1 : 0);
        __syncthreads();

        if (c + 2 < L) {
            uint32_t dtb = sb + sload * STAGE_BYTES;
            int ko = (c + 2) * BK;
            cp16(dtb + so0, pA + ko);
            cp16(dtb + so1, pA + ko + 8);
            if (TERMS == 2) {
                cp16(dtb + SUB_BYTES + so0, pA + KP + ko);
                cp16(dtb + SUB_BYTES + so1, pA + KP + ko + 8);
            }
            cp16(dtb + TERMS * SUB_BYTES + so0, pB + ko);
            cp16(dtb + TERMS * SUB_BYTES + so1, pB + ko + 8);
            CP_COMMIT();
        }

        uint32_t stb = sb + s * STAGE_BYTES;
#pragma unroll
        for (int ks = 0; ks < 2; ks++) {
            uint32_t ao = stb + (aoff00 ^ (ks * 32));
            uint32_t bo = stb + (boff00 ^ (ks * 32));
            uint32_t ahi[2][4], alo[2][4], bfr[4][4];
            ldsm4(ahi[0], ao);
            ldsm4(ahi[1], ao + 1024);
            if (TERMS == 2) {
                ldsm4(alo[0], ao + SUB_BYTES);
                ldsm4(alo[1], ao + SUB_BYTES + 1024);
            }
#pragma unroll
            for (int g = 0; g < 4; g++) ldsm4(bfr[g], bo + g * 1024);
#pragma unroll
            for (int g = 0; g < 4; g++)
#pragma unroll
                for (int h = 0; h < 2; h++)
#pragma unroll
                    for (int mi = 0; mi < 2; mi++)
                        mma_f32acc(acc[mi][g * 2 + h], ahi[mi], bfr[g][h], bfr[g][h + 2]);
            if (TERMS == 2) {
#pragma unroll
                for (int g = 0; g < 4; g++)
#pragma unroll
                    for (int h = 0; h < 2; h++)
#pragma unroll
                        for (int mi = 0; mi < 2; mi++)
                            mma_f32acc(acc[mi][g * 2 + h], alo[mi], bfr[g][h], bfr[g][h + 2]);
            }
        }
        s++; if (s == STG) s = 0;
        sload++; if (sload == STG) sload = 0;
    }

    // epilogue
    int erow0 = gm * BM + warp_m * 32 + (lane >> 2);
    int ecol0 = gn * BN + warp_n * 64 + (lane & 3) * 2;
#pragma unroll
    for (int mi = 0; mi < 2; mi++) {
#pragma unroll
        for (int ni = 0; ni < 8; ni++) {
            int r = erow0 + mi * 16;
            int cc = ecol0 + ni * 8;
#pragma unroll
            for (int half_i = 0; half_i < 2; half_i++) {
                int rr = r + half_i * 8;
                if (rr < M && cc < N) {
                    float o0 = acc[mi][ni][half_i * 2 + 0];
                    float o1 = acc[mi][ni][half_i * 2 + 1];
                    size_t idx = (size_t)rr * ldc + cc;
                    if (flags & 16) {
                        atomicAdd(&C[idx], o0);
                        atomicAdd(&C[idx + 1], o1);
                    } else {
                        if (flags & 1) { o0 += bias[cc]; o1 += bias[cc + 1]; }
                        if (flags & 2) { o0 = fmaxf(o0, 0.f); o1 = fmaxf(o1, 0.f); }
                        if (!(flags & 8)) { C[idx] = o0; C[idx + 1] = o1; }
                        if (flags & 4)
                            *reinterpret_cast<__half2*>(&C16[idx]) = __floats2half2_rn(o0, o1);
                    }
                }
            }
        }
    }
}

// ---------------- conversion kernels ----------------
__device__ __forceinline__ uint32_t pack_h2(__half a, __half b) {
    return ((uint32_t)__half_as_ushort(b) << 16) | __half_as_ushort(a);
}

// A[M,K] fp32 -> [Mp, KP] fp16 hi only (1-term A panel)
__global__ void k_splitA1(const float* __restrict__ src, __half* __restrict__ dst,
                          int M, int K, int KP)
{
    int k = (blockIdx.x * 256 + threadIdx.x) * 4;
    int m = blockIdx.y;
    if (k >= KP) return;
    float4 v = make_float4(0.f, 0.f, 0.f, 0.f);
    if (m < M && k < K) v = *reinterpret_cast<const float4*>(&src[(size_t)m * K + k]);
    uint2 hp;
    hp.x = pack_h2(__float2half_rn(v.x), __float2half_rn(v.y));
    hp.y = pack_h2(__float2half_rn(v.z), __float2half_rn(v.w));
    *reinterpret_cast<uint2*>(&dst[(size_t)m * KP + k]) = hp;
}

// B[K,N] fp32 -> transposed [Np, KP] fp16 hi only
__global__ void k_splitBT2(const float* __restrict__ src, __half* __restrict__ dst,
                           int K, int N, int KP)
{
    __shared__ float t[64][33];
    int k0 = blockIdx.x * 64, n0 = blockIdx.y * 32;
    int tx = threadIdx.x, ty = threadIdx.y;
#pragma unroll
    for (int it = 0; it < 8; it++) {
        int k = k0 + ty + it * 8;
        int n = n0 + tx;
        t[ty + it * 8][tx] = (k < K && n < N) ? src[(size_t)k * N + n] : 0.f;
    }
    __syncthreads();
    int uid = ty * 32 + tx;
    int nl = uid >> 3;
    int kg = (uid & 7) * 8;
    size_t base = (size_t)(n0 + nl) * KP + k0;
#pragma unroll
    for (int q = 0; q < 4; q++) {
        int kk = kg + q * 2;
        float v0 = t[kk][nl], v1 = t[kk + 1][nl];
        *reinterpret_cast<uint32_t*>(&dst[base + kk]) =
            pack_h2(__float2half_rn(v0), __float2half_rn(v1));
    }
}

// ---------------- scalar SGEMM ----------------
__global__ __launch_bounds__(256) void sgemm(const float* __restrict__ A,
                                             const float* __restrict__ B,
                                             const float* __restrict__ bias,
                                             float* __restrict__ C,
                                             int M, int N, int K,
                                             int hasBias, int doRelu) {
    __shared__ float As[8][128];
    __shared__ float Bs[8][128];
    const int tid   = threadIdx.x;
    const int tileM = blockIdx.y * 128;
    const int tileN = blockIdx.x * 128;

    const int aRow = tid >> 1;
    const int aK4  = (tid & 1) * 4;
    const int bRow = tid >> 5;
    const int bCol = (tid & 31) * 4;
    const int ty   = tid >> 4;
    const int tx   = tid & 15;

    float acc[8][8];
#pragma unroll
    for (int i = 0; i < 8; i++)
#pragma unroll
        for (int j = 0; j < 8; j++) acc[i][j] = 0.f;

    for (int k0 = 0; k0 < K; k0 += 8) {
        float4 av = make_float4(0.f, 0.f, 0.f, 0.f);
        int gr = tileM + aRow;
        if (gr < M) av = *reinterpret_cast<const float4*>(&A[(size_t)gr * K + k0 + aK4]);
        As[aK4 + 0][aRow] = av.x;
        As[aK4 + 1][aRow] = av.y;
        As[aK4 + 2][aRow] = av.z;
        As[aK4 + 3][aRow] = av.w;

        float4 bv = make_float4(0.f, 0.f, 0.f, 0.f);
        int gc = tileN + bCol;
        const float* bp = &B[(size_t)(k0 + bRow) * N + gc];
        if (gc + 3 < N) {
            bv = *reinterpret_cast<const float4*>(bp);
        } else {
            if (gc + 0 < N) bv.x = bp[0];
            if (gc + 1 < N) bv.y = bp[1];
            if (gc + 2 < N) bv.z = bp[2];
            if (gc + 3 < N) bv.w = bp[3];
        }
        *reinterpret_cast<float4*>(&Bs[bRow][bCol]) = bv;

        __syncthreads();
#pragma unroll
        for (int kk = 0; kk < 8; kk++) {
            float a[8], b[8];
            *reinterpret_cast<float4*>(&a[0]) = *reinterpret_cast<float4*>(&As[kk][ty * 8]);
            *reinterpret_cast<float4*>(&a[4]) = *reinterpret_cast<float4*>(&As[kk][ty * 8 + 4]);
            *reinterpret_cast<float4*>(&b[0]) = *reinterpret_cast<float4*>(&Bs[kk][tx * 8]);
            *reinterpret_cast<float4*>(&b[4]) = *reinterpret_cast<float4*>(&Bs[kk][tx * 8 + 4]);
#pragma unroll
            for (int i = 0; i < 8; i++)
#pragma unroll
                for (int j = 0; j < 8; j++) acc[i][j] = fmaf(a[i], b[j], acc[i][j]);
        }
        __syncthreads();
    }

#pragma unroll
    for (int i = 0; i < 8; i++) {
        int row = tileM + ty * 8 + i;
        if (row >= M) continue;
#pragma unroll
        for (int j = 0; j < 8; j++) {
            int col = tileN + tx * 8 + j;
            if (col < N) {
                float v = acc[i][j];
                if (hasBias) v += bias[col];
                if (doRelu) v = fmaxf(v, 0.f);
                C[(size_t)row * N + col] = v;
            }
        }
    }
}

// ---------------- attention pre-projection ----------------
__global__ void k_wtilde(const float* __restrict__ W, const float* __restrict__ a_s,
                         const float* __restrict__ a_d) {
    int i = blockIdx.x;
    int w = threadIdx.x >> 5;
    int lane = threadIdx.x & 31;
    if (w >= HH) return;
    const float* row = W + (size_t)i * HFD + w * FF;
    const float* as  = a_s + w * FF;
    const float* ad  = a_d + w * FF;
    float s1 = 0.f, s2 = 0.f;
    for (int f = lane; f < FF; f += 32) {
        float v = row[f];
        s1 = fmaf(v, as[f], s1);
        s2 = fmaf(v, ad[f], s2);
    }
#pragma unroll
    for (int o = 16; o; o >>= 1) {
        s1 += __shfl_down_sync(0xffffffffu, s1, o);
        s2 += __shfl_down_sync(0xffffffffu, s2, o);
    }
    if (lane == 0) { g_wt[i * 20 + w] = s1; g_wt[i * 20 + 10 + w] = s2; }
}

// ---------------- MLP1 bias-fill + relu ----------------
__global__ void k_fill_bias512(float* __restrict__ dst, const float* __restrict__ bias) {
    int i = blockIdx.x * 256 + threadIdx.x;
    if (i < GG * 512) dst[i] = bias[i & 511];
}
__global__ void k_relu_small(float* __restrict__ a, int n) {
    int i = blockIdx.x * 256 + threadIdx.x;
    if (i < n) a[i] = fmaxf(a[i], 0.f);
}

// ---------------- CSR build ----------------
__global__ void k_init() {
    int i = blockIdx.x * blockDim.x + threadIdx.x;
    if (i < NN) { g_cnt[i] = 0; g_cur[i] = 0; }
    if (i < GG) { g_pstart[i] = 0x7fffffff; g_pend[i] = -1; g_pcnt[i] = 0; }
}

__global__ void k_count(const int* __restrict__ ei) {
    int k = blockIdx.x * blockDim.x + threadIdx.x;
    if (k >= ETOT) return;
    int dst = (k < EE) ? ei[EE + k] : (k - EE);
    atomicAdd(&g_cnt[dst], 1);
}

__global__ __launch_bounds__(1024) void k_scan() {
    __shared__ int sd[1024];
    __shared__ int scarry;
    int tid = threadIdx.x;
    if (tid == 0) { scarry = 0; g_start[0] = 0; }
    __syncthreads();
    for (int base = 0; base < NN; base += 1024) {
        int v = (base + tid < NN) ? g_cnt[base + tid] : 0;
        sd[tid] = v;
        __syncthreads();
        for (int o = 1; o < 1024; o <<= 1) {
            int t = (tid >= o) ? sd[tid - o] : 0;
            __syncthreads();
            sd[tid] += t;
            __syncthreads();
        }
        int run = scarry;
        if (base + tid < NN) g_start[base + tid + 1] = run + sd[tid];
        __syncthreads();
        if (tid == 1023) scarry = run + sd[1023];
        __syncthreads();
    }
}

__global__ void k_scatter(const int* __restrict__ ei) {
    int k = blockIdx.x * blockDim.x + threadIdx.x;
    if (k >= ETOT) return;
    int src = (k < EE) ? ei[k]      : (k - EE);
    int dst = (k < EE) ? ei[EE + k] : (k - EE);
    int pos = g_start[dst] + atomicAdd(&g_cur[dst], 1);
    g_esrc[pos] = src;
}

__global__ void k_dinv() {
    int i = blockIdx.x * blockDim.x + threadIdx.x;
    if (i < NN) g_dinv[i] = rsqrtf((float)g_cnt[i]);
}

// ---------------- softmax ----------------
__global__ void k_softmax() {
    int node = blockIdx.x * blockDim.y + threadIdx.y;
    if (node >= NN) return;
    int lane = threadIdx.x;
    bool act = lane < HH;
    int s = g_start[node], e = g_start[node + 1];
    float ald_v = act ? g_al[node * 20 + 10 + lane] : 0.f;
    float mx = -3.0e38f;
    for (int p = s; p < e; p++) {
        int src = g_esrc[p];
        if (act) {
            float v = g_al[src * 20 + lane] + ald_v;
            v = fmaxf(v, 0.2f * v);
            mx = fmaxf(mx, v);
        }
    }
    float z = 0.f;
    for (int p = s; p < e; p++) {
        int src = g_esrc[p];
        if (act) {
            float v = g_al[src * 20 + lane] + ald_v;
            v = fmaxf(v, 0.2f * v);
            float ex = expf(v - mx);
            g_alpha[(size_t)p * HH + lane] = ex;
            z += ex;
        }
    }
    float inv = 1.f / (z + 1e-16f);
    for (int p = s; p < e; p++)
        if (act) g_alpha[(size_t)p * HH + lane] *= inv;
}

// ---------------- GAT aggregation (fp16 gather) -> hi-only fp16 A panel ----------------
__global__ __launch_bounds__(256) void k_gat_agg_split(const float* __restrict__ bias) {
    int n = blockIdx.x, tid = threadIdx.x;
    __half* arow = s_a2 + (size_t)n * KP2;
    if (n >= NN) {
        for (int k = tid; k < KP2 / 2; k += 256)
            reinterpret_cast<uint32_t*>(arow)[k] = 0;
        return;
    }
    int s = g_start[n], e = g_start[n + 1];
    float2 acc[PCH];
    int hidx[PCH];
#pragma unroll
    for (int i = 0; i < PCH; i++) {
        int f = 2 * tid + 512 * i;
        hidx[i] = (f < HFD) ? (f / FF) : 0;
        acc[i].x = (f < HFD) ? bias[f] : 0.f;
        acc[i].y = (f + 1 < HFD) ? bias[f + 1] : 0.f;
    }
    for (int p = s; p < e; p++) {
        int src = g_esrc[p];
        const __half2* xr = reinterpret_cast<const __half2*>(g_xh16 + (size_t)src * HFD);
        const float* al = g_alpha + (size_t)p * HH;
#pragma unroll
        for (int i = 0; i < PCH; i++) {
            int f = 2 * tid + 512 * i;
            if (f < HFD) {
                float2 v = __half22float2(xr[f >> 1]);
                float a = al[hidx[i]];
                acc[i].x = fmaf(a, v.x, acc[i].x);
                acc[i].y = fmaf(a, v.y, acc[i].y);
            }
        }
    }
#pragma unroll
    for (int i = 0; i < PCH; i++) {
        int f = 2 * tid + 512 * i;
        if (f < KP2) {
            float vx = (f < HFD) ? fmaxf(acc[i].x, 0.f) : 0.f;
            float vy = (f + 1 < HFD) ? fmaxf(acc[i].y, 0.f) : 0.f;
            *reinterpret_cast<uint32_t*>(&arow[f]) =
                pack_h2(__float2half_rn(vx), __float2half_rn(vy));
        }
    }
}

// ---------------- GCN aggregation (fp16 gather, fp16 out) ----------------
__global__ __launch_bounds__(256) void k_gcn_agg(const float* __restrict__ bias) {
    int n = blockIdx.x, tid = threadIdx.x;
    int s = g_start[n], e = g_start[n + 1];
    float dv = g_dinv[n];
    float2 acc[PCH];
#pragma unroll
    for (int i = 0; i < PCH; i++) {
        int f = 2 * tid + 512 * i;
        acc[i].x = (f < HFD) ? bias[f] : 0.f;
        acc[i].y = (f + 1 < HFD) ? bias[f + 1] : 0.f;
    }
    for (int p = s; p < e; p++) {
        int src = g_esrc[p];
        float coef = g_dinv[src] * dv;
        const __half2* xr = reinterpret_cast<const __half2*>(g_xw16 + (size_t)src * HFD);
#pragma unroll
        for (int i = 0; i < PCH; i++) {
            int f = 2 * tid + 512 * i;
            if (f < HFD) {
                float2 v = __half22float2(xr[f >> 1]);
                acc[i].x = fmaf(coef, v.x, acc[i].x);
                acc[i].y = fmaf(coef, v.y, acc[i].y);
            }
        }
    }
    __half2* o = reinterpret_cast<__half2*>(g_h216 + (size_t)n * HFD);
#pragma unroll
    for (int i = 0; i < PCH; i++) {
        int f = 2 * tid + 512 * i;
        if (f < HFD)
            o[f >> 1] = __floats2half2_rn(fmaxf(acc[i].x, 0.f), fmaxf(acc[i].y, 0.f));
    }
}

// ---------------- pooling fused with MLP1 A-panel split ----------------
__global__ void k_ranges(const int* __restrict__ batch) {
    int i = blockIdx.x * blockDim.x + threadIdx.x;
    if (i >= NN) return;
    int b = batch[i];
    if (b >= 0 && b < GG) {
        atomicMin(&g_pstart[b], i);
        atomicMax(&g_pend[b], i);
        atomicAdd(&g_pcnt[b], 1);
    }
}

__device__ __forceinline__ void h_split_store(__half* hi, __half* lo, float v) {
    __half h = __float2half_rn(v);
    *hi = h;
    *lo = __float2half_rn(v - __half2float(h));
}

__global__ __launch_bounds__(256) void k_pool_split() {
    int g = blockIdx.y;
    int f = blockIdx.x * blockDim.x + threadIdx.x;
    if (f >= HFD) return;
    int s = g_pstart[g], e = g_pend[g];
    float mx = -3.0e38f, sm = 0.f;
    for (int n = s; n <= e; n++) {
        float v = __half2float(g_h216[(size_t)n * HFD + f]);
        mx = fmaxf(mx, v);
        sm += v;
    }
    float gap = sm / (float)g_pcnt[g];
    __half* row = s_a2 + (size_t)g * (2 * KPM);
    h_split_store(&row[f],       &row[KPM + f],       mx);
    h_split_store(&row[HFD + f], &row[KPM + HFD + f], gap);
}

__global__ void k_pool_pad() {
    int g = blockIdx.x;
    int t = threadIdx.x;
    __half* row = s_a2 + (size_t)g * (2 * KPM);
    row[HF2 + t] = __float2half_rn(0.f);
    row[KPM + HF2 + t] = __float2half_rn(0.f);
}

// ---------------- launch ----------------
extern "C" void kernel_launch(void* const* d_in, const int* in_sizes, int n_in,
                              void* d_out, int out_size) {
    const float* x     = (const float*)d_in[0];
    const int*   ei    = (const int*)  d_in[1];
    const int*   batch = (const int*)  d_in[2];
    const float* W_gat = (const float*)d_in[3];
    const float* a_src = (const float*)d_in[4];
    const float* a_dst = (const float*)d_in[5];
    const float* b_gat = (const float*)d_in[6];
    const float* W_gcn = (const float*)d_in[7];
    const float* b_gcn = (const float*)d_in[8];
    const float* W1    = (const float*)d_in[9];
    const float* b1    = (const float*)d_in[10];
    const float* W2    = (const float*)d_in[11];
    const float* b2    = (const float*)d_in[12];
    const float* W3    = (const float*)d_in[13];
    const float* b3    = (const float*)d_in[14];
    float* out = (float*)d_out;

    float *p_wt, *p_al, *p_m1, *p_m2;
    __half *p_xh16, *p_xw16, *p_a2, *p_b2;
    cudaGetSymbolAddress((void**)&p_wt,   g_wt);
    cudaGetSymbolAddress((void**)&p_al,   g_al);
    cudaGetSymbolAddress((void**)&p_xh16, g_xh16);
    cudaGetSymbolAddress((void**)&p_xw16, g_xw16);
    cudaGetSymbolAddress((void**)&p_m1,   g_mlp1);
    cudaGetSymbolAddress((void**)&p_m2,   g_mlp2);
    cudaGetSymbolAddress((void**)&p_a2,   s_a2);
    cudaGetSymbolAddress((void**)&p_b2,   s_b2);

    cudaFuncSetAttribute(mma_gemm<2>, cudaFuncAttributeMaxDynamicSharedMemorySize, SMEM_MMA_2);
    cudaFuncSetAttribute(mma_gemm<1>, cudaFuncAttributeMaxDynamicSharedMemorySize, SMEM_MMA_1);

    const int TM = MP_G / 128;   // 63
    const int TN = NPAD / 128;   // 54

    // ---- GEMM1 (1-term): xh16 = x @ W_gat (fp16-only); mma at launch idx 3 ----
    {
        dim3 gA((KP1 / 4 + 255) / 256, MP_G);
        k_splitA1<<<gA, 256>>>(x, p_a2, NN, FF, KP1);                 // 0
        dim3 gB(KP1 / 64, NPAD / 32);
        k_splitBT2<<<gB, dim3(32, 8)>>>(W_gat, p_b2, FF, HFD, KP1);   // 1
    }
    k_init<<<(NN + 255) / 256, 256>>>();                               // 2
    mma_gemm<1><<<TM * TN, 256, SMEM_MMA_1>>>(p_a2, p_b2, nullptr, nullptr, p_xh16,  // 3
                                              NN, HFD, HFD, KP1, TM, TN, 4 | 8, KP1 / 32);

    // attention logits via pre-projection (exact fp32 path)
    k_wtilde<<<FF, 320>>>(W_gat, a_src, a_dst);
    {
        dim3 grid(1, (NN + 127) / 128);
        sgemm<<<grid, 256>>>(x, p_wt, nullptr, p_al, NN, 20, FF, 0, 0);
    }

    // CSR build + degrees
    k_count<<<(ETOT + 255) / 256, 256>>>(ei);
    k_scan<<<1, 1024>>>();
    k_scatter<<<(ETOT + 255) / 256, 256>>>(ei);
    k_dinv<<<(NN + 255) / 256, 256>>>();

    k_softmax<<<(NN + 7) / 8, dim3(32, 8)>>>();
    k_gat_agg_split<<<MP_G, 256>>>(b_gat);

    // ---- GEMM2 (1-term): xw16 = h @ W_gcn (fp16-only store) ----
    {
        dim3 gB(KP2 / 64, NPAD / 32);
        k_splitBT2<<<gB, dim3(32, 8)>>>(W_gcn, p_b2, HFD, HFD, KP2);
        mma_gemm<1><<<TM * TN, 256, SMEM_MMA_1>>>(p_a2, p_b2, nullptr, nullptr, p_xw16,
                                                  NN, HFD, HFD, KP2, TM, TN, 4 | 8, KP2 / 32);
    }

    k_gcn_agg<<<NN, 256>>>(b_gcn);   // fp16 gather, fp16 h2 out

    // pooling (fp16 read, writes MLP1 A-panel hi/lo)
    k_ranges<<<(NN + 255) / 256, 256>>>(batch);
    {
        dim3 grid((HFD + 255) / 256, GG);
        k_pool_split<<<grid, 256>>>();
        k_pool_pad<<<GG, 32>>>();
    }

    // ---- MLP1 (2-term, split-K): g_mlp1 = relu(pool @ W1 + b1) ----
    {
        dim3 gB(KPM / 64, 512 / 32);
        k_splitBT2<<<gB, dim3(32, 8)>>>(W1, p_b2, HF2, 512, KPM);
        k_fill_bias512<<<(GG * 512 + 255) / 256, 256>>>(p_m1, b1);
        mma_gemm<2><<<dim3(2 * 4, 16), 256, SMEM_MMA_2>>>(p_a2, p_b2, nullptr, p_m1, nullptr,
                                                          GG, 512, 512, KPM, 2, 4, 16, 27);
        k_relu_small<<<(GG * 512 + 255) / 256, 256>>>(p_m1, GG * 512);
    }

    // MLP tail (tiny)
    {
        dim3 grid(1, 2);
        sgemm<<<grid, 256>>>(p_m1, W2, b2, p_m2, GG, 128, 512, 1, 0);
    }
    {
        dim3 grid(1, 2);
        sgemm<<<grid, 256>>>(p_m2, W3, b3, out, GG, 64, 128, 1, 0);
    }
}